// round 1
// baseline (speedup 1.0000x reference)
#include <cuda_runtime.h>
#include <math.h>

#define NN 50000
#define EE 300000
#define IND 128
#define HFD 64
#define AHD 4
#define RRD 3
#define HD 256          // HF*AH
#define RN (RRD*NN)
#define RE (RRD*EE)
#define NB ((RN+1023)/1024)   // scan blocks = 147

// ---------------- scratch (device globals; no allocation) ----------------
__device__ __align__(16) float g_hw[(size_t)RRD*NN*HD];      // 153.6 MB
__device__ __align__(16) float g_outbuf[(size_t)NN*RRD*HD];  // 153.6 MB
__device__ int   g_counts[RN];
__device__ int   g_rowptr[RN];
__device__ int   g_cursor[RN];
__device__ int   g_srclist[RE];
__device__ __align__(16) float g_P1[NN];
__device__ __align__(16) float g_P2[NN];
__device__ __align__(16) float g_Q1[RN*AHD];
__device__ __align__(16) float g_Q2[RN*AHD];
__device__ __align__(16) float g_u1[IND];
__device__ __align__(16) float g_u2[IND];
__device__ __align__(16) float g_v1[RRD*AHD*IND];
__device__ __align__(16) float g_v2[RRD*AHD*IND];
__device__ float g_cq1[RRD*AHD];
__device__ float g_cq2[RRD*AHD];
__device__ float g_cscore;
__device__ int   g_bsums[256];

// ---------------- helpers ----------------
__device__ __forceinline__ unsigned long long f2pk(float lo, float hi) {
    unsigned long long r;
    asm("mov.b64 %0, {%1, %2};" : "=l"(r) : "f"(lo), "f"(hi));
    return r;
}
__device__ __forceinline__ unsigned long long ffma2(unsigned long long a,
                                                    unsigned long long b,
                                                    unsigned long long c) {
    unsigned long long d;
    asm("fma.rn.f32x2 %0, %1, %2, %3;" : "=l"(d) : "l"(a), "l"(b), "l"(c));
    return d;
}
__device__ __forceinline__ void f2up(unsigned long long v, float& lo, float& hi) {
    asm("mov.b64 {%0, %1}, %2;" : "=f"(lo), "=f"(hi) : "l"(v));
}
__device__ __forceinline__ float warpdot(float h0, float h1, float h2, float h3,
                                         const float* __restrict__ v, int lane) {
    float s = h0*v[lane] + h1*v[lane+32] + h2*v[lane+64] + h3*v[lane+96];
    #pragma unroll
    for (int o = 16; o; o >>= 1) s += __shfl_xor_sync(0xffffffffu, s, o);
    return s;
}

// ---------------- CSR construction ----------------
__global__ void k_zero() {
    int i = blockIdx.x*blockDim.x + threadIdx.x;
    if (i < RN) { g_counts[i] = 0; g_cursor[i] = 0; }
}

__global__ void k_hist(const int* __restrict__ dst) {
    int t = blockIdx.x*blockDim.x + threadIdx.x;
    if (t < RE) {
        int r = t / EE;
        atomicAdd(&g_counts[r*NN + dst[t]], 1);
    }
}

__global__ void k_scan1() {
    __shared__ int sm[1024];
    int tid = threadIdx.x;
    int i = blockIdx.x*1024 + tid;
    int v = (i < RN) ? g_counts[i] : 0;
    sm[tid] = v; __syncthreads();
    for (int off = 1; off < 1024; off <<= 1) {
        int t = (tid >= off) ? sm[tid-off] : 0;
        __syncthreads();
        sm[tid] += t; __syncthreads();
    }
    if (i < RN) g_rowptr[i] = sm[tid] - v;
    if (tid == 1023) g_bsums[blockIdx.x] = sm[1023];
}

__global__ void k_scan2() {
    __shared__ int sm[256];
    int tid = threadIdx.x;
    int v = (tid < NB) ? g_bsums[tid] : 0;
    sm[tid] = v; __syncthreads();
    for (int off = 1; off < 256; off <<= 1) {
        int t = (tid >= off) ? sm[tid-off] : 0;
        __syncthreads();
        sm[tid] += t; __syncthreads();
    }
    if (tid < NB) g_bsums[tid] = sm[tid] - v;
}

__global__ void k_scan3() {
    int i = blockIdx.x*1024 + threadIdx.x;
    if (i < RN) g_rowptr[i] += g_bsums[blockIdx.x];
}

__global__ void k_scatter(const int* __restrict__ src, const int* __restrict__ dst) {
    int t = blockIdx.x*blockDim.x + threadIdx.x;
    if (t < RE) {
        int r = t / EE;
        int i = r*NN + dst[t];
        int pos = g_rowptr[i] + atomicAdd(&g_cursor[i], 1);
        g_srclist[pos] = src[t];
    }
}

// ---------------- small projection vectors ----------------
// u1 = dW @ (fW0 + fW2) ; u2 = dW @ (fW1 - fW2)
// v1[r,a] = wW[r][:, a*64:(a+1)*64] @ aW[r][0:64] ; v2 uses aW[r][64:128]
__global__ void k_vecs(const float* __restrict__ dW, const float* __restrict__ db,
                       const float* __restrict__ fW, const float* __restrict__ fb,
                       const float* __restrict__ wW, const float* __restrict__ wb,
                       const float* __restrict__ aW, const float* __restrict__ ab) {
    int i = threadIdx.x;  // 0..127
    float u1 = 0.f, u2 = 0.f;
    for (int j = 0; j < HD; j++) {
        float d  = dW[i*HD + j];
        float f0 = fW[j], f1 = fW[HD + j], f2 = fW[2*HD + j];
        u1 += d * (f0 + f2);
        u2 += d * (f1 - f2);
    }
    g_u1[i] = u1; g_u2[i] = u2;
    for (int r = 0; r < RRD; r++) {
        const float* a1 = aW + r*2*HFD;
        const float* a2 = a1 + HFD;
        for (int a = 0; a < AHD; a++) {
            const float* wp = wW + ((size_t)(r*IND + i))*HD + a*HFD;
            float v1 = 0.f, v2 = 0.f;
            for (int k = 0; k < HFD; k++) { v1 += wp[k]*a1[k]; v2 += wp[k]*a2[k]; }
            g_v1[(r*AHD + a)*IND + i] = v1;
            g_v2[(r*AHD + a)*IND + i] = v2;
        }
    }
    if (i == 0) {
        float c = fb[0];
        for (int j = 0; j < HD; j++) c += db[j] * (fW[j] + fW[HD + j]);
        g_cscore = c;
    }
    if (i < RRD*AHD) {
        int r = i / AHD, a = i % AHD;
        const float* wbp = wb + r*HD + a*HFD;
        const float* a1 = aW + r*2*HFD;
        const float* a2 = a1 + HFD;
        float c1 = 0.f, c2 = 0.f;
        for (int k = 0; k < HFD; k++) { c1 += wbp[k]*a1[k]; c2 += wbp[k]*a2[k]; }
        g_cq1[i] = c1;
        g_cq2[i] = c2 + ab[r];
    }
}

// ---------------- per-node scalars P1,P2,Q1,Q2 ----------------
__global__ void k_node(const float* __restrict__ h) {
    int warp = threadIdx.x >> 5, lane = threadIdx.x & 31;
    int n = blockIdx.x*8 + warp;
    const float* hp = h + (size_t)n*IND;
    float h0 = hp[lane], h1 = hp[lane+32], h2 = hp[lane+64], h3 = hp[lane+96];
    float p1 = warpdot(h0, h1, h2, h3, g_u1, lane);
    float p2 = warpdot(h0, h1, h2, h3, g_u2, lane);
    if (lane == 0) { g_P1[n] = p1; g_P2[n] = p2; }
    for (int ra = 0; ra < RRD*AHD; ra++) {
        float q1 = warpdot(h0, h1, h2, h3, g_v1 + ra*IND, lane);
        float q2 = warpdot(h0, h1, h2, h3, g_v2 + ra*IND, lane);
        if (lane == 0) {
            int r = ra / AHD, a = ra % AHD;
            g_Q1[(r*NN + n)*AHD + a] = q1 + g_cq1[ra];
            g_Q2[(r*NN + n)*AHD + a] = q2 + g_cq2[ra];
        }
    }
}

// ---------------- fp32 GEMM, C = A@B + bias, f32x2-packed inner ----------------
__global__ void k_gemm(const float* __restrict__ A, const float* __restrict__ B,
                       const float* __restrict__ bias, float* __restrict__ C,
                       int M, int Ncols, int K,
                       long long strideB, long long strideBias, long long strideC) {
    B    += (size_t)blockIdx.z * strideB;
    bias += (size_t)blockIdx.z * strideBias;
    C    += (size_t)blockIdx.z * strideC;
    __shared__ __align__(16) float As[16][64];
    __shared__ __align__(16) float Bs[16][64];
    int tid = threadIdx.x;                 // 256 threads
    int brow = blockIdx.x*64, bcol = blockIdx.y*64;
    int ty = tid >> 4, tx = tid & 15;
    int lar = tid >> 2;                    // 0..63
    int lak = (tid & 3) << 2;              // 0,4,8,12
    int lbk = tid >> 4;                    // 0..15
    int lbc = (tid & 15) << 2;             // 0..60
    unsigned long long acc2[4][2];
    #pragma unroll
    for (int i = 0; i < 4; i++) { acc2[i][0] = 0ull; acc2[i][1] = 0ull; }

    for (int k0 = 0; k0 < K; k0 += 16) {
        int ar = brow + lar;
        float4 av = (ar < M) ? *(const float4*)(A + (size_t)ar*K + k0 + lak)
                             : make_float4(0.f, 0.f, 0.f, 0.f);
        As[lak+0][lar] = av.x; As[lak+1][lar] = av.y;
        As[lak+2][lar] = av.z; As[lak+3][lar] = av.w;
        *(float4*)&Bs[lbk][lbc] = *(const float4*)(B + (size_t)(k0 + lbk)*Ncols + bcol + lbc);
        __syncthreads();
        #pragma unroll
        for (int kk = 0; kk < 16; kk++) {
            float4 a4 = *(const float4*)&As[kk][ty << 2];
            float4 b4 = *(const float4*)&Bs[kk][tx << 2];
            unsigned long long b01 = f2pk(b4.x, b4.y);
            unsigned long long b23 = f2pk(b4.z, b4.w);
            unsigned long long aa;
            aa = f2pk(a4.x, a4.x); acc2[0][0] = ffma2(aa, b01, acc2[0][0]); acc2[0][1] = ffma2(aa, b23, acc2[0][1]);
            aa = f2pk(a4.y, a4.y); acc2[1][0] = ffma2(aa, b01, acc2[1][0]); acc2[1][1] = ffma2(aa, b23, acc2[1][1]);
            aa = f2pk(a4.z, a4.z); acc2[2][0] = ffma2(aa, b01, acc2[2][0]); acc2[2][1] = ffma2(aa, b23, acc2[2][1]);
            aa = f2pk(a4.w, a4.w); acc2[3][0] = ffma2(aa, b01, acc2[3][0]); acc2[3][1] = ffma2(aa, b23, acc2[3][1]);
        }
        __syncthreads();
    }
    float4 bv = *(const float4*)(bias + bcol + (tx << 2));
    #pragma unroll
    for (int i = 0; i < 4; i++) {
        int rr = brow + (ty << 2) + i;
        if (rr < M) {
            float c0, c1, c2, c3;
            f2up(acc2[i][0], c0, c1);
            f2up(acc2[i][1], c2, c3);
            float4 o = make_float4(c0 + bv.x, c1 + bv.y, c2 + bv.z, c3 + bv.w);
            *(float4*)(C + (size_t)rr*Ncols + bcol + (tx << 2)) = o;
        }
    }
}

// ---------------- edge aggregation: one warp per (node, relation) ----------------
__global__ void k_edge() {
    int r = blockIdx.y;
    int warp = threadIdx.x >> 5, lane = threadIdx.x & 31;
    int n = blockIdx.x*8 + warp;
    int idx = r*NN + n;
    float acc[8];
    #pragma unroll
    for (int k = 0; k < 8; k++) acc[k] = 0.f;

    int deg = g_counts[idx];
    if (deg > 0) {
        int base = g_rowptr[idx];
        float p2 = g_P2[n] + g_cscore;
        float4 q2 = *(const float4*)&g_Q2[idx*AHD];

        // pass 1: softmax denominators (4 heads)
        float d0 = 0.f, d1 = 0.f, d2 = 0.f, d3 = 0.f;
        for (int j = lane; j < deg; j += 32) {
            int s = g_srclist[base + j];
            float sc = g_P1[s] + p2;
            float sg = (sc > 0.f) ? 1.f : ((sc < 0.f) ? -1.f : 0.f);
            float4 q1 = *(const float4*)&g_Q1[(r*NN + s)*AHD];
            float a0 = sg*q1.x + q2.x; a0 = (a0 >= 0.f) ? a0 : 0.01f*a0;
            float a1 = sg*q1.y + q2.y; a1 = (a1 >= 0.f) ? a1 : 0.01f*a1;
            float a2 = sg*q1.z + q2.z; a2 = (a2 >= 0.f) ? a2 : 0.01f*a2;
            float a3 = sg*q1.w + q2.w; a3 = (a3 >= 0.f) ? a3 : 0.01f*a3;
            d0 += expf(a0); d1 += expf(a1); d2 += expf(a2); d3 += expf(a3);
        }
        #pragma unroll
        for (int o = 16; o; o >>= 1) {
            d0 += __shfl_xor_sync(0xffffffffu, d0, o);
            d1 += __shfl_xor_sync(0xffffffffu, d1, o);
            d2 += __shfl_xor_sync(0xffffffffu, d2, o);
            d3 += __shfl_xor_sync(0xffffffffu, d3, o);
        }
        float i0 = 1.f/d0, i1 = 1.f/d1, i2 = 1.f/d2, i3 = 1.f/d3;

        // pass 2: weighted feature gather/accumulate
        const float* hwr = g_hw + (size_t)r*NN*HD;
        int hl = lane >> 3;   // head owned by this lane's 8 columns
        for (int c0 = 0; c0 < deg; c0 += 32) {
            int j = c0 + lane;
            int s = 0;
            float w0 = 0.f, w1 = 0.f, w2 = 0.f, w3 = 0.f;
            if (j < deg) {
                s = g_srclist[base + j];
                float sc = g_P1[s] + p2;
                float sg = (sc > 0.f) ? 1.f : ((sc < 0.f) ? -1.f : 0.f);
                float4 q1 = *(const float4*)&g_Q1[(r*NN + s)*AHD];
                float a0 = sg*q1.x + q2.x; a0 = (a0 >= 0.f) ? a0 : 0.01f*a0;
                float a1 = sg*q1.y + q2.y; a1 = (a1 >= 0.f) ? a1 : 0.01f*a1;
                float a2 = sg*q1.z + q2.z; a2 = (a2 >= 0.f) ? a2 : 0.01f*a2;
                float a3 = sg*q1.w + q2.w; a3 = (a3 >= 0.f) ? a3 : 0.01f*a3;
                w0 = sg * expf(a0) * i0;
                w1 = sg * expf(a1) * i1;
                w2 = sg * expf(a2) * i2;
                w3 = sg * expf(a3) * i3;
            }
            int m = min(32, deg - c0);
            for (int jj = 0; jj < m; jj++) {
                int   sb = __shfl_sync(0xffffffffu, s,  jj);
                float t0 = __shfl_sync(0xffffffffu, w0, jj);
                float t1 = __shfl_sync(0xffffffffu, w1, jj);
                float t2 = __shfl_sync(0xffffffffu, w2, jj);
                float t3 = __shfl_sync(0xffffffffu, w3, jj);
                float wh = (hl == 0) ? t0 : ((hl == 1) ? t1 : ((hl == 2) ? t2 : t3));
                const float4* pp = (const float4*)(hwr + (size_t)sb*HD + lane*8);
                float4 x0 = pp[0], x1 = pp[1];
                acc[0] += wh*x0.x; acc[1] += wh*x0.y; acc[2] += wh*x0.z; acc[3] += wh*x0.w;
                acc[4] += wh*x1.x; acc[5] += wh*x1.y; acc[6] += wh*x1.z; acc[7] += wh*x1.w;
            }
        }
    }
    float* op = g_outbuf + (size_t)n*(RRD*HD) + r*HD + lane*8;
    *(float4*)op       = make_float4(acc[0], acc[1], acc[2], acc[3]);
    *(float4*)(op + 4) = make_float4(acc[4], acc[5], acc[6], acc[7]);
}

// ---------------- launch ----------------
extern "C" void kernel_launch(void* const* d_in, const int* in_sizes, int n_in,
                              void* d_out, int out_size) {
    const float* h    = (const float*)d_in[0];
    const float* dW   = (const float*)d_in[1];
    const float* db   = (const float*)d_in[2];
    const float* fW   = (const float*)d_in[3];
    const float* fb   = (const float*)d_in[4];
    const float* wW   = (const float*)d_in[5];
    const float* wb   = (const float*)d_in[6];
    const float* aW   = (const float*)d_in[7];
    const float* ab   = (const float*)d_in[8];
    const float* linW = (const float*)d_in[9];
    const float* linb = (const float*)d_in[10];
    const int*   src  = (const int*)d_in[11];
    const int*   dst  = (const int*)d_in[12];
    float* out = (float*)d_out;

    float* hwp = nullptr;
    float* obp = nullptr;
    cudaGetSymbolAddress((void**)&hwp, g_hw);
    cudaGetSymbolAddress((void**)&obp, g_outbuf);

    k_zero<<<(RN + 255)/256, 256>>>();
    k_hist<<<(RE + 255)/256, 256>>>(dst);
    k_scan1<<<NB, 1024>>>();
    k_scan2<<<1, 256>>>();
    k_scan3<<<NB, 1024>>>();
    k_scatter<<<(RE + 255)/256, 256>>>(src, dst);
    k_vecs<<<1, 128>>>(dW, db, fW, fb, wW, wb, aW, ab);
    k_node<<<NN/8, 256>>>(h);

    dim3 g1((NN + 63)/64, HD/64, RRD);
    k_gemm<<<g1, 256>>>(h, wW, wb, hwp, NN, HD, IND,
                        (long long)IND*HD, (long long)HD, (long long)NN*HD);

    dim3 g2(NN/8, RRD);
    k_edge<<<g2, 256>>>();

    dim3 g3((NN + 63)/64, HD/64, 1);
    k_gemm<<<g3, 256>>>(obp, linW, linb, out, NN, HD, RRD*HD, 0, 0, 0);
}

// round 3
// speedup vs baseline: 1.4847x; 1.4847x over previous
#include <cuda_runtime.h>
#include <cuda_bf16.h>
#include <math.h>
#include <stdint.h>

#define NN 50000
#define EE 300000
#define IND 128
#define HFD 64
#define AHD 4
#define RRD 3
#define HD 256          // HF*AH
#define RN (RRD*NN)
#define RE (RRD*EE)
#define NB ((RN+1023)/1024)   // scan blocks = 147

// ---------------- scratch (device globals; no allocation) ----------------
__device__ __align__(16) float g_hw[(size_t)RRD*NN*HD];            // 153.6 MB fp32
__device__ __align__(16) __nv_bfloat16 g_hhi[(size_t)NN*IND];      // h split
__device__ __align__(16) __nv_bfloat16 g_hlo[(size_t)NN*IND];
__device__ __align__(16) __nv_bfloat16 g_a2hi[(size_t)NN*RRD*HD];  // edge-out split
__device__ __align__(16) __nv_bfloat16 g_a2lo[(size_t)NN*RRD*HD];
__device__ __align__(16) __nv_bfloat16 g_w1hi[RRD*HD*IND];         // wW^T  [R,256,128]
__device__ __align__(16) __nv_bfloat16 g_w1lo[RRD*HD*IND];
__device__ __align__(16) __nv_bfloat16 g_w2hi[HD*RRD*HD];          // linW^T [256,768]
__device__ __align__(16) __nv_bfloat16 g_w2lo[HD*RRD*HD];
__device__ int   g_counts[RN];
__device__ int   g_rowptr[RN];
__device__ int   g_cursor[RN];
__device__ int   g_srclist[RE];
__device__ __align__(16) float g_P1[NN];
__device__ __align__(16) float g_P2[NN];
__device__ __align__(16) float g_Q1[RN*AHD];
__device__ __align__(16) float g_Q2[RN*AHD];
__device__ __align__(16) float g_u1[IND];
__device__ __align__(16) float g_u2[IND];
__device__ __align__(16) float g_v1[RRD*AHD*IND];
__device__ __align__(16) float g_v2[RRD*AHD*IND];
__device__ float g_cq1[RRD*AHD];
__device__ float g_cq2[RRD*AHD];
__device__ float g_cscore;
__device__ int   g_bsums[256];

// ---------------- helpers ----------------
__device__ __forceinline__ float warpdot(float h0, float h1, float h2, float h3,
                                         const float* __restrict__ v, int lane) {
    float s = h0*v[lane] + h1*v[lane+32] + h2*v[lane+64] + h3*v[lane+96];
    #pragma unroll
    for (int o = 16; o; o >>= 1) s += __shfl_xor_sync(0xffffffffu, s, o);
    return s;
}

// mma.sync m16n8k16 bf16 (accumulate in-place)
__device__ __forceinline__ void mma16816(float* c, const uint32_t* a, const uint32_t* b) {
    asm volatile("mma.sync.aligned.m16n8k16.row.col.f32.bf16.bf16.f32 "
                 "{%0,%1,%2,%3}, {%4,%5,%6,%7}, {%8,%9}, {%0,%1,%2,%3};"
                 : "+f"(c[0]), "+f"(c[1]), "+f"(c[2]), "+f"(c[3])
                 : "r"(a[0]), "r"(a[1]), "r"(a[2]), "r"(a[3]), "r"(b[0]), "r"(b[1]));
}

// ---------------- CSR construction ----------------
__global__ void k_zero() {
    int i = blockIdx.x*blockDim.x + threadIdx.x;
    if (i < RN) { g_counts[i] = 0; g_cursor[i] = 0; }
}
__global__ void k_hist(const int* __restrict__ dst) {
    int t = blockIdx.x*blockDim.x + threadIdx.x;
    if (t < RE) {
        int r = t / EE;
        atomicAdd(&g_counts[r*NN + dst[t]], 1);
    }
}
__global__ void k_scan1() {
    __shared__ int sm[1024];
    int tid = threadIdx.x;
    int i = blockIdx.x*1024 + tid;
    int v = (i < RN) ? g_counts[i] : 0;
    sm[tid] = v; __syncthreads();
    for (int off = 1; off < 1024; off <<= 1) {
        int t = (tid >= off) ? sm[tid-off] : 0;
        __syncthreads();
        sm[tid] += t; __syncthreads();
    }
    if (i < RN) g_rowptr[i] = sm[tid] - v;
    if (tid == 1023) g_bsums[blockIdx.x] = sm[1023];
}
__global__ void k_scan2() {
    __shared__ int sm[256];
    int tid = threadIdx.x;
    int v = (tid < NB) ? g_bsums[tid] : 0;
    sm[tid] = v; __syncthreads();
    for (int off = 1; off < 256; off <<= 1) {
        int t = (tid >= off) ? sm[tid-off] : 0;
        __syncthreads();
        sm[tid] += t; __syncthreads();
    }
    if (tid < NB) g_bsums[tid] = sm[tid] - v;
}
__global__ void k_scan3() {
    int i = blockIdx.x*1024 + threadIdx.x;
    if (i < RN) g_rowptr[i] += g_bsums[blockIdx.x];
}
__global__ void k_scatter(const int* __restrict__ src, const int* __restrict__ dst) {
    int t = blockIdx.x*blockDim.x + threadIdx.x;
    if (t < RE) {
        int r = t / EE;
        int i = r*NN + dst[t];
        int pos = g_rowptr[i] + atomicAdd(&g_cursor[i], 1);
        g_srclist[pos] = src[t];
    }
}

// ---------------- small projection vectors ----------------
__global__ void k_vecs(const float* __restrict__ dW, const float* __restrict__ db,
                       const float* __restrict__ fW, const float* __restrict__ fb,
                       const float* __restrict__ wW, const float* __restrict__ wb,
                       const float* __restrict__ aW, const float* __restrict__ ab) {
    int i = threadIdx.x;  // 0..127
    float u1 = 0.f, u2 = 0.f;
    for (int j = 0; j < HD; j++) {
        float d  = dW[i*HD + j];
        float f0 = fW[j], f1 = fW[HD + j], f2 = fW[2*HD + j];
        u1 += d * (f0 + f2);
        u2 += d * (f1 - f2);
    }
    g_u1[i] = u1; g_u2[i] = u2;
    for (int r = 0; r < RRD; r++) {
        const float* a1 = aW + r*2*HFD;
        const float* a2 = a1 + HFD;
        for (int a = 0; a < AHD; a++) {
            const float* wp = wW + ((size_t)(r*IND + i))*HD + a*HFD;
            float v1 = 0.f, v2 = 0.f;
            for (int k = 0; k < HFD; k++) { v1 += wp[k]*a1[k]; v2 += wp[k]*a2[k]; }
            g_v1[(r*AHD + a)*IND + i] = v1;
            g_v2[(r*AHD + a)*IND + i] = v2;
        }
    }
    if (i == 0) {
        float c = fb[0];
        for (int j = 0; j < HD; j++) c += db[j] * (fW[j] + fW[HD + j]);
        g_cscore = c;
    }
    if (i < RRD*AHD) {
        int r = i / AHD, a = i % AHD;
        const float* wbp = wb + r*HD + a*HFD;
        const float* a1 = aW + r*2*HFD;
        const float* a2 = a1 + HFD;
        float c1 = 0.f, c2 = 0.f;
        for (int k = 0; k < HFD; k++) { c1 += wbp[k]*a1[k]; c2 += wbp[k]*a2[k]; }
        g_cq1[i] = c1;
        g_cq2[i] = c2 + ab[r];
    }
}

// ---------------- per-node scalars (exact fp32; feeds sign()) ----------------
__global__ void k_node(const float* __restrict__ h) {
    int warp = threadIdx.x >> 5, lane = threadIdx.x & 31;
    int n = blockIdx.x*8 + warp;
    const float* hp = h + (size_t)n*IND;
    float h0 = hp[lane], h1 = hp[lane+32], h2 = hp[lane+64], h3 = hp[lane+96];
    float p1 = warpdot(h0, h1, h2, h3, g_u1, lane);
    float p2 = warpdot(h0, h1, h2, h3, g_u2, lane);
    if (lane == 0) { g_P1[n] = p1; g_P2[n] = p2; }
    for (int ra = 0; ra < RRD*AHD; ra++) {
        float q1 = warpdot(h0, h1, h2, h3, g_v1 + ra*IND, lane);
        float q2 = warpdot(h0, h1, h2, h3, g_v2 + ra*IND, lane);
        if (lane == 0) {
            int r = ra / AHD, a = ra % AHD;
            g_Q1[(r*NN + n)*AHD + a] = q1 + g_cq1[ra];
            g_Q2[(r*NN + n)*AHD + a] = q2 + g_cq2[ra];
        }
    }
}

// ---------------- operand prep: split h, transpose+split B matrices ----------------
__global__ void k_split_h(const float* __restrict__ h) {
    int t = blockIdx.x*blockDim.x + threadIdx.x;   // over NN*IND/4
    if (t >= NN*IND/4) return;
    float4 v = *(const float4*)(h + (size_t)t*4);
    __nv_bfloat16 hi[4], lo[4];
    float x[4] = {v.x, v.y, v.z, v.w};
    #pragma unroll
    for (int k = 0; k < 4; k++) {
        hi[k] = __float2bfloat16(x[k]);
        lo[k] = __float2bfloat16(x[k] - __bfloat162float(hi[k]));
    }
    *(uint2*)(g_hhi + (size_t)t*4) = *(uint2*)hi;
    *(uint2*)(g_hlo + (size_t)t*4) = *(uint2*)lo;
}

__global__ void k_transB(const float* __restrict__ wW, const float* __restrict__ linW) {
    int t = blockIdx.x*blockDim.x + threadIdx.x;
    const int W1 = RRD*HD*IND;      // 98304
    const int W2 = HD*RRD*HD;       // 196608
    if (t < W1) {
        int r = t / (HD*IND);
        int rem = t % (HD*IND);
        int n = rem / IND, k = rem % IND;
        float x = wW[((size_t)r*IND + k)*HD + n];
        __nv_bfloat16 hi = __float2bfloat16(x);
        g_w1hi[t] = hi;
        g_w1lo[t] = __float2bfloat16(x - __bfloat162float(hi));
    } else if (t < W1 + W2) {
        int t2 = t - W1;
        int n = t2 / (RRD*HD), k = t2 % (RRD*HD);
        float x = linW[(size_t)k*HD + n];
        __nv_bfloat16 hi = __float2bfloat16(x);
        g_w2hi[t2] = hi;
        g_w2lo[t2] = __float2bfloat16(x - __bfloat162float(hi));
    }
}

// ---------------- mma.sync bf16-split GEMM: C[M,256] = A[M,K] @ B^T + bias ------
// A: bf16 hi/lo [M,K] row-major. B: bf16 hi/lo [256,K] row-major (pre-transposed).
// CTA 128x128, 8 warps 4(M)x2(N), warp 32x64, K-chunk 32.
// 3 fragment passes: hi*hi + hi*lo + lo*hi into shared fp32 accumulators.
#define APAD 40   // bf16 row stride in smem (80B, 8B-aligned, conflict-free)

__global__ void __launch_bounds__(256, 1) k_gemm_mma(
    const __nv_bfloat16* __restrict__ Ahi, const __nv_bfloat16* __restrict__ Alo,
    const __nv_bfloat16* __restrict__ Bhi, const __nv_bfloat16* __restrict__ Blo,
    const float* __restrict__ bias, float* __restrict__ C,
    int M, int K,
    long long strideB, long long strideBias, long long strideC)
{
    Bhi  += (size_t)blockIdx.z * strideB;
    Blo  += (size_t)blockIdx.z * strideB;
    bias += (size_t)blockIdx.z * strideBias;
    C    += (size_t)blockIdx.z * strideC;

    __shared__ __nv_bfloat16 Ash[2][128][APAD];   // [hi/lo][m][k]
    __shared__ __nv_bfloat16 Bsh[2][128][APAD];   // [hi/lo][n][k]

    int tid = threadIdx.x, wid = tid >> 5, lane = tid & 31;
    int g = lane >> 2, tg = lane & 3;
    int row0 = blockIdx.x * 128, col0 = blockIdx.y * 128;
    int wm = (wid & 3) * 32;       // warp M offset in tile
    int wn = (wid >> 2) * 64;      // warp N offset in tile

    float acc[2][8][4];
    #pragma unroll
    for (int i = 0; i < 2; i++)
        #pragma unroll
        for (int j = 0; j < 8; j++)
            #pragma unroll
            for (int q = 0; q < 4; q++) acc[i][j][q] = 0.f;

    int nch = K >> 5;
    for (int c = 0; c < nch; c++) {
        int gk0 = c << 5;
        // load A/B tiles: 128 rows x 32 bf16 each; 512 uint4 per buffer, 2/thread
        #pragma unroll
        for (int it = 0; it < 2; it++) {
            int idx = it*256 + tid;
            int rr = idx >> 2, cq = (idx & 3) << 3;   // row, col in bf16 units
            int gr = row0 + rr;
            uint4 vh = make_uint4(0,0,0,0), vl = make_uint4(0,0,0,0);
            if (gr < M) {
                size_t go = (size_t)gr*K + gk0 + cq;
                vh = *(const uint4*)(Ahi + go);
                vl = *(const uint4*)(Alo + go);
            }
            *(uint2*)&Ash[0][rr][cq]   = make_uint2(vh.x, vh.y);
            *(uint2*)&Ash[0][rr][cq+4] = make_uint2(vh.z, vh.w);
            *(uint2*)&Ash[1][rr][cq]   = make_uint2(vl.x, vl.y);
            *(uint2*)&Ash[1][rr][cq+4] = make_uint2(vl.z, vl.w);
            size_t gb = (size_t)(col0 + rr)*K + gk0 + cq;   // always in-range (Ncols=256)
            uint4 wh = *(const uint4*)(Bhi + gb);
            uint4 wl = *(const uint4*)(Blo + gb);
            *(uint2*)&Bsh[0][rr][cq]   = make_uint2(wh.x, wh.y);
            *(uint2*)&Bsh[0][rr][cq+4] = make_uint2(wh.z, wh.w);
            *(uint2*)&Bsh[1][rr][cq]   = make_uint2(wl.x, wl.y);
            *(uint2*)&Bsh[1][rr][cq+4] = make_uint2(wl.z, wl.w);
        }
        __syncthreads();

        #pragma unroll
        for (int ks = 0; ks < 2; ks++) {
            int k0 = (ks << 4) + tg*2;
            uint32_t Ah[2][4], Al[2][4];
            #pragma unroll
            for (int i = 0; i < 2; i++) {
                int rb = wm + i*16 + g;
                Ah[i][0] = *(const uint32_t*)&Ash[0][rb  ][k0];
                Ah[i][1] = *(const uint32_t*)&Ash[0][rb+8][k0];
                Ah[i][2] = *(const uint32_t*)&Ash[0][rb  ][k0+8];
                Ah[i][3] = *(const uint32_t*)&Ash[0][rb+8][k0+8];
                Al[i][0] = *(const uint32_t*)&Ash[1][rb  ][k0];
                Al[i][1] = *(const uint32_t*)&Ash[1][rb+8][k0];
                Al[i][2] = *(const uint32_t*)&Ash[1][rb  ][k0+8];
                Al[i][3] = *(const uint32_t*)&Ash[1][rb+8][k0+8];
            }
            uint32_t Bh[8][2], Bl[8][2];
            #pragma unroll
            for (int j = 0; j < 8; j++) {
                int nb = wn + j*8 + g;
                Bh[j][0] = *(const uint32_t*)&Bsh[0][nb][k0];
                Bh[j][1] = *(const uint32_t*)&Bsh[0][nb][k0+8];
                Bl[j][0] = *(const uint32_t*)&Bsh[1][nb][k0];
                Bl[j][1] = *(const uint32_t*)&Bsh[1][nb][k0+8];
            }
            #pragma unroll
            for (int i = 0; i < 2; i++)
                #pragma unroll
                for (int j = 0; j < 8; j++) {
                    mma16816(acc[i][j], Ah[i], Bh[j]);
                    mma16816(acc[i][j], Ah[i], Bl[j]);
                    mma16816(acc[i][j], Al[i], Bh[j]);
                }
        }
        __syncthreads();
    }

    // epilogue
    #pragma unroll
    for (int i = 0; i < 2; i++) {
        int r0r = row0 + wm + i*16 + g;
        #pragma unroll
        for (int j = 0; j < 8; j++) {
            int cc = col0 + wn + j*8 + tg*2;
            float b0 = bias[cc], b1 = bias[cc+1];
            if (r0r < M) {
                float2 o = make_float2(acc[i][j][0] + b0, acc[i][j][1] + b1);
                *(float2*)(C + (size_t)r0r*HD + cc) = o;
            }
            if (r0r + 8 < M) {
                float2 o = make_float2(acc[i][j][2] + b0, acc[i][j][3] + b1);
                *(float2*)(C + (size_t)(r0r+8)*HD + cc) = o;
            }
        }
    }
}

// ---------------- edge aggregation: one warp per (node, relation) ----------------
__global__ void k_edge() {
    int r = blockIdx.y;
    int warp = threadIdx.x >> 5, lane = threadIdx.x & 31;
    int n = blockIdx.x*8 + warp;
    int idx = r*NN + n;
    float acc[8];
    #pragma unroll
    for (int k = 0; k < 8; k++) acc[k] = 0.f;

    int deg = g_counts[idx];
    if (deg > 0) {
        int base = g_rowptr[idx];
        float p2 = g_P2[n] + g_cscore;
        float4 q2 = *(const float4*)&g_Q2[idx*AHD];

        // pass 1: softmax denominators (4 heads)
        float d0 = 0.f, d1 = 0.f, d2 = 0.f, d3 = 0.f;
        for (int j = lane; j < deg; j += 32) {
            int s = g_srclist[base + j];
            float sc = g_P1[s] + p2;
            float sg = (sc > 0.f) ? 1.f : ((sc < 0.f) ? -1.f : 0.f);
            float4 q1 = *(const float4*)&g_Q1[(r*NN + s)*AHD];
            float a0 = sg*q1.x + q2.x; a0 = (a0 >= 0.f) ? a0 : 0.01f*a0;
            float a1 = sg*q1.y + q2.y; a1 = (a1 >= 0.f) ? a1 : 0.01f*a1;
            float a2 = sg*q1.z + q2.z; a2 = (a2 >= 0.f) ? a2 : 0.01f*a2;
            float a3 = sg*q1.w + q2.w; a3 = (a3 >= 0.f) ? a3 : 0.01f*a3;
            d0 += expf(a0); d1 += expf(a1); d2 += expf(a2); d3 += expf(a3);
        }
        #pragma unroll
        for (int o = 16; o; o >>= 1) {
            d0 += __shfl_xor_sync(0xffffffffu, d0, o);
            d1 += __shfl_xor_sync(0xffffffffu, d1, o);
            d2 += __shfl_xor_sync(0xffffffffu, d2, o);
            d3 += __shfl_xor_sync(0xffffffffu, d3, o);
        }
        float i0 = 1.f/d0, i1 = 1.f/d1, i2 = 1.f/d2, i3 = 1.f/d3;

        // pass 2: weighted feature gather/accumulate
        const float* hwr = g_hw + (size_t)r*NN*HD;
        int hl = lane >> 3;
        for (int c0 = 0; c0 < deg; c0 += 32) {
            int j = c0 + lane;
            int s = 0;
            float w0 = 0.f, w1 = 0.f, w2 = 0.f, w3 = 0.f;
            if (j < deg) {
                s = g_srclist[base + j];
                float sc = g_P1[s] + p2;
                float sg = (sc > 0.f) ? 1.f : ((sc < 0.f) ? -1.f : 0.f);
                float4 q1 = *(const float4*)&g_Q1[(r*NN + s)*AHD];
                float a0 = sg*q1.x + q2.x; a0 = (a0 >= 0.f) ? a0 : 0.01f*a0;
                float a1 = sg*q1.y + q2.y; a1 = (a1 >= 0.f) ? a1 : 0.01f*a1;
                float a2 = sg*q1.z + q2.z; a2 = (a2 >= 0.f) ? a2 : 0.01f*a2;
                float a3 = sg*q1.w + q2.w; a3 = (a3 >= 0.f) ? a3 : 0.01f*a3;
                w0 = sg * expf(a0) * i0;
                w1 = sg * expf(a1) * i1;
                w2 = sg * expf(a2) * i2;
                w3 = sg * expf(a3) * i3;
            }
            int m = min(32, deg - c0);
            for (int jj = 0; jj < m; jj++) {
                int   sbn = __shfl_sync(0xffffffffu, s,  jj);
                float t0 = __shfl_sync(0xffffffffu, w0, jj);
                float t1 = __shfl_sync(0xffffffffu, w1, jj);
                float t2 = __shfl_sync(0xffffffffu, w2, jj);
                float t3 = __shfl_sync(0xffffffffu, w3, jj);
                float wh = (hl == 0) ? t0 : ((hl == 1) ? t1 : ((hl == 2) ? t2 : t3));
                const float4* pp = (const float4*)(hwr + (size_t)sbn*HD + lane*8);
                float4 x0 = pp[0], x1 = pp[1];
                acc[0] += wh*x0.x; acc[1] += wh*x0.y; acc[2] += wh*x0.z; acc[3] += wh*x0.w;
                acc[4] += wh*x1.x; acc[5] += wh*x1.y; acc[6] += wh*x1.z; acc[7] += wh*x1.w;
            }
        }
    }
    // write bf16 hi/lo split directly (feeds GEMM2 A operand)
    __nv_bfloat16 hi[8], lo[8];
    #pragma unroll
    for (int k = 0; k < 8; k++) {
        hi[k] = __float2bfloat16(acc[k]);
        lo[k] = __float2bfloat16(acc[k] - __bfloat162float(hi[k]));
    }
    size_t ofs = (size_t)n*(RRD*HD) + r*HD + lane*8;
    *(uint4*)(g_a2hi + ofs) = *(uint4*)hi;
    *(uint4*)(g_a2lo + ofs) = *(uint4*)lo;
}

// ---------------- launch ----------------
extern "C" void kernel_launch(void* const* d_in, const int* in_sizes, int n_in,
                              void* d_out, int out_size) {
    const float* h    = (const float*)d_in[0];
    const float* dW   = (const float*)d_in[1];
    const float* db   = (const float*)d_in[2];
    const float* fW   = (const float*)d_in[3];
    const float* fb   = (const float*)d_in[4];
    const float* wW   = (const float*)d_in[5];
    const float* wb   = (const float*)d_in[6];
    const float* aW   = (const float*)d_in[7];
    const float* ab   = (const float*)d_in[8];
    const float* linW = (const float*)d_in[9];
    const float* linb = (const float*)d_in[10];
    const int*   src  = (const int*)d_in[11];
    const int*   dst  = (const int*)d_in[12];
    float* out = (float*)d_out;

    float *hwp = nullptr;
    __nv_bfloat16 *hhi, *hlo, *a2hi, *a2lo, *w1hi, *w1lo, *w2hi, *w2lo;
    cudaGetSymbolAddress((void**)&hwp,  g_hw);
    cudaGetSymbolAddress((void**)&hhi,  g_hhi);
    cudaGetSymbolAddress((void**)&hlo,  g_hlo);
    cudaGetSymbolAddress((void**)&a2hi, g_a2hi);
    cudaGetSymbolAddress((void**)&a2lo, g_a2lo);
    cudaGetSymbolAddress((void**)&w1hi, g_w1hi);
    cudaGetSymbolAddress((void**)&w1lo, g_w1lo);
    cudaGetSymbolAddress((void**)&w2hi, g_w2hi);
    cudaGetSymbolAddress((void**)&w2lo, g_w2lo);

    k_zero<<<(RN + 255)/256, 256>>>();
    k_hist<<<(RE + 255)/256, 256>>>(dst);
    k_scan1<<<NB, 1024>>>();
    k_scan2<<<1, 256>>>();
    k_scan3<<<NB, 1024>>>();
    k_scatter<<<(RE + 255)/256, 256>>>(src, dst);
    k_vecs<<<1, 128>>>(dW, db, fW, fb, wW, wb, aW, ab);
    k_node<<<NN/8, 256>>>(h);
    k_split_h<<<(NN*IND/4 + 255)/256, 256>>>(h);
    k_transB<<<(RRD*HD*IND + HD*RRD*HD + 255)/256, 256>>>(wW, linW);

    // GEMM1: hw[r] = h @ wW[r] + wb[r]   (M=50000, K=128, N=256, z over relations)
    dim3 g1((NN + 127)/128, 2, RRD);
    k_gemm_mma<<<g1, 256>>>(hhi, hlo, w1hi, w1lo, wb, hwp,
                            NN, IND,
                            (long long)HD*IND, (long long)HD,
                            (long long)NN*HD);

    dim3 g2(NN/8, RRD);
    k_edge<<<g2, 256>>>();

    // GEMM2: out = a2 @ linW + linb      (M=50000, K=768, N=256)
    dim3 g3((NN + 127)/128, 2, 1);
    k_gemm_mma<<<g3, 256>>>(a2hi, a2lo, w2hi, w2lo, linb, out,
                            NN, RRD*HD, 0, 0, 0);
}

// round 4
// speedup vs baseline: 1.7638x; 1.1880x over previous
#include <cuda_runtime.h>
#include <cuda_bf16.h>
#include <math.h>
#include <stdint.h>

#define NN 50000
#define EE 300000
#define IND 128
#define HFD 64
#define AHD 4
#define RRD 3
#define HD 256          // HF*AH
#define RN (RRD*NN)
#define RE (RRD*EE)
#define NB ((RN+1023)/1024)   // scan blocks = 147

// ---------------- scratch (device globals; no allocation) ----------------
__device__ __align__(16) float g_hw[(size_t)RRD*NN*HD];            // 153.6 MB fp32
__device__ __align__(16) __nv_bfloat16 g_hhi[(size_t)NN*IND];      // h split
__device__ __align__(16) __nv_bfloat16 g_hlo[(size_t)NN*IND];
__device__ __align__(16) __nv_bfloat16 g_a2hi[(size_t)NN*RRD*HD];  // edge-out split
__device__ __align__(16) __nv_bfloat16 g_a2lo[(size_t)NN*RRD*HD];
__device__ __align__(16) __nv_bfloat16 g_w1hi[RRD*HD*IND];         // wW^T  [R,256,128]
__device__ __align__(16) __nv_bfloat16 g_w1lo[RRD*HD*IND];
__device__ __align__(16) __nv_bfloat16 g_w2hi[HD*RRD*HD];          // linW^T [256,768]
__device__ __align__(16) __nv_bfloat16 g_w2lo[HD*RRD*HD];
__device__ int   g_counts[RN];
__device__ int   g_rowptr[RN];
__device__ int   g_cursor[RN];
__device__ int   g_srclist[RE];
__device__ __align__(16) float g_P1[NN];
__device__ __align__(16) float g_P2[NN];
__device__ __align__(16) float g_Q1[RN*AHD];
__device__ __align__(16) float g_Q2[RN*AHD];
__device__ __align__(16) float g_u1[IND];
__device__ __align__(16) float g_u2[IND];
__device__ __align__(16) float g_v1[RRD*AHD*IND];
__device__ __align__(16) float g_v2[RRD*AHD*IND];
__device__ float g_cq1[RRD*AHD];
__device__ float g_cq2[RRD*AHD];
__device__ float g_cscore;
__device__ int   g_bsums[256];

// ---------------- helpers ----------------
__device__ __forceinline__ float warpdot(float h0, float h1, float h2, float h3,
                                         const float* __restrict__ v, int lane) {
    float s = h0*v[lane] + h1*v[lane+32] + h2*v[lane+64] + h3*v[lane+96];
    #pragma unroll
    for (int o = 16; o; o >>= 1) s += __shfl_xor_sync(0xffffffffu, s, o);
    return s;
}

__device__ __forceinline__ uint32_t smaddr(const void* p) {
    uint32_t a;
    asm("{ .reg .u64 t; cvta.to.shared.u64 t, %1; cvt.u32.u64 %0, t; }" : "=r"(a) : "l"(p));
    return a;
}
__device__ __forceinline__ void cp16(uint32_t d, const void* s, int sz) {
    asm volatile("cp.async.cg.shared.global [%0], [%1], 16, %2;" :: "r"(d), "l"(s), "r"(sz));
}

// mma.sync m16n8k16 bf16 (accumulate in-place)
__device__ __forceinline__ void mma16816(float* c, const uint32_t* a, const uint32_t* b) {
    asm volatile("mma.sync.aligned.m16n8k16.row.col.f32.bf16.bf16.f32 "
                 "{%0,%1,%2,%3}, {%4,%5,%6,%7}, {%8,%9}, {%0,%1,%2,%3};"
                 : "+f"(c[0]), "+f"(c[1]), "+f"(c[2]), "+f"(c[3])
                 : "r"(a[0]), "r"(a[1]), "r"(a[2]), "r"(a[3]), "r"(b[0]), "r"(b[1]));
}

// ---------------- CSR construction ----------------
__global__ void k_zero() {
    int i = blockIdx.x*blockDim.x + threadIdx.x;
    if (i < RN) { g_counts[i] = 0; g_cursor[i] = 0; }
}
__global__ void k_hist(const int* __restrict__ dst) {
    int t = blockIdx.x*blockDim.x + threadIdx.x;
    if (t < RE) {
        int r = t / EE;
        atomicAdd(&g_counts[r*NN + dst[t]], 1);
    }
}
__global__ void k_scan1() {
    __shared__ int sm[1024];
    int tid = threadIdx.x;
    int i = blockIdx.x*1024 + tid;
    int v = (i < RN) ? g_counts[i] : 0;
    sm[tid] = v; __syncthreads();
    for (int off = 1; off < 1024; off <<= 1) {
        int t = (tid >= off) ? sm[tid-off] : 0;
        __syncthreads();
        sm[tid] += t; __syncthreads();
    }
    if (i < RN) g_rowptr[i] = sm[tid] - v;
    if (tid == 1023) g_bsums[blockIdx.x] = sm[1023];
}
__global__ void k_scan2() {
    __shared__ int sm[256];
    int tid = threadIdx.x;
    int v = (tid < NB) ? g_bsums[tid] : 0;
    sm[tid] = v; __syncthreads();
    for (int off = 1; off < 256; off <<= 1) {
        int t = (tid >= off) ? sm[tid-off] : 0;
        __syncthreads();
        sm[tid] += t; __syncthreads();
    }
    if (tid < NB) g_bsums[tid] = sm[tid] - v;
}
__global__ void k_scan3() {
    int i = blockIdx.x*1024 + threadIdx.x;
    if (i < RN) g_rowptr[i] += g_bsums[blockIdx.x];
}
__global__ void k_scatter(const int* __restrict__ src, const int* __restrict__ dst) {
    int t = blockIdx.x*blockDim.x + threadIdx.x;
    if (t < RE) {
        int r = t / EE;
        int i = r*NN + dst[t];
        int pos = g_rowptr[i] + atomicAdd(&g_cursor[i], 1);
        g_srclist[pos] = src[t];
    }
}

// ---------------- small projection vectors ----------------
__global__ void k_vecs(const float* __restrict__ dW, const float* __restrict__ db,
                       const float* __restrict__ fW, const float* __restrict__ fb,
                       const float* __restrict__ wW, const float* __restrict__ wb,
                       const float* __restrict__ aW, const float* __restrict__ ab) {
    int i = threadIdx.x;  // 0..127
    float u1 = 0.f, u2 = 0.f;
    for (int j = 0; j < HD; j++) {
        float d  = dW[i*HD + j];
        float f0 = fW[j], f1 = fW[HD + j], f2 = fW[2*HD + j];
        u1 += d * (f0 + f2);
        u2 += d * (f1 - f2);
    }
    g_u1[i] = u1; g_u2[i] = u2;
    for (int r = 0; r < RRD; r++) {
        const float* a1 = aW + r*2*HFD;
        const float* a2 = a1 + HFD;
        for (int a = 0; a < AHD; a++) {
            const float* wp = wW + ((size_t)(r*IND + i))*HD + a*HFD;
            float v1 = 0.f, v2 = 0.f;
            for (int k = 0; k < HFD; k++) { v1 += wp[k]*a1[k]; v2 += wp[k]*a2[k]; }
            g_v1[(r*AHD + a)*IND + i] = v1;
            g_v2[(r*AHD + a)*IND + i] = v2;
        }
    }
    if (i == 0) {
        float c = fb[0];
        for (int j = 0; j < HD; j++) c += db[j] * (fW[j] + fW[HD + j]);
        g_cscore = c;
    }
    if (i < RRD*AHD) {
        int r = i / AHD, a = i % AHD;
        const float* wbp = wb + r*HD + a*HFD;
        const float* a1 = aW + r*2*HFD;
        const float* a2 = a1 + HFD;
        float c1 = 0.f, c2 = 0.f;
        for (int k = 0; k < HFD; k++) { c1 += wbp[k]*a1[k]; c2 += wbp[k]*a2[k]; }
        g_cq1[i] = c1;
        g_cq2[i] = c2 + ab[r];
    }
}

// ---------------- per-node scalars (exact fp32; feeds sign()) ----------------
__global__ void k_node(const float* __restrict__ h) {
    int warp = threadIdx.x >> 5, lane = threadIdx.x & 31;
    int n = blockIdx.x*8 + warp;
    const float* hp = h + (size_t)n*IND;
    float h0 = hp[lane], h1 = hp[lane+32], h2 = hp[lane+64], h3 = hp[lane+96];
    float p1 = warpdot(h0, h1, h2, h3, g_u1, lane);
    float p2 = warpdot(h0, h1, h2, h3, g_u2, lane);
    if (lane == 0) { g_P1[n] = p1; g_P2[n] = p2; }
    for (int ra = 0; ra < RRD*AHD; ra++) {
        float q1 = warpdot(h0, h1, h2, h3, g_v1 + ra*IND, lane);
        float q2 = warpdot(h0, h1, h2, h3, g_v2 + ra*IND, lane);
        if (lane == 0) {
            int r = ra / AHD, a = ra % AHD;
            g_Q1[(r*NN + n)*AHD + a] = q1 + g_cq1[ra];
            g_Q2[(r*NN + n)*AHD + a] = q2 + g_cq2[ra];
        }
    }
}

// ---------------- operand prep: split h, transpose+split B matrices ----------------
__global__ void k_split_h(const float* __restrict__ h) {
    int t = blockIdx.x*blockDim.x + threadIdx.x;   // over NN*IND/4
    if (t >= NN*IND/4) return;
    float4 v = *(const float4*)(h + (size_t)t*4);
    __nv_bfloat16 hi[4], lo[4];
    float x[4] = {v.x, v.y, v.z, v.w};
    #pragma unroll
    for (int k = 0; k < 4; k++) {
        hi[k] = __float2bfloat16(x[k]);
        lo[k] = __float2bfloat16(x[k] - __bfloat162float(hi[k]));
    }
    *(uint2*)(g_hhi + (size_t)t*4) = *(uint2*)hi;
    *(uint2*)(g_hlo + (size_t)t*4) = *(uint2*)lo;
}

__global__ void k_transB(const float* __restrict__ wW, const float* __restrict__ linW) {
    int t = blockIdx.x*blockDim.x + threadIdx.x;
    const int W1 = RRD*HD*IND;      // 98304
    const int W2 = HD*RRD*HD;       // 196608
    if (t < W1) {
        int r = t / (HD*IND);
        int rem = t % (HD*IND);
        int n = rem / IND, k = rem % IND;
        float x = wW[((size_t)r*IND + k)*HD + n];
        __nv_bfloat16 hi = __float2bfloat16(x);
        g_w1hi[t] = hi;
        g_w1lo[t] = __float2bfloat16(x - __bfloat162float(hi));
    } else if (t < W1 + W2) {
        int t2 = t - W1;
        int n = t2 / (RRD*HD), k = t2 % (RRD*HD);
        float x = linW[(size_t)k*HD + n];
        __nv_bfloat16 hi = __float2bfloat16(x);
        g_w2hi[t2] = hi;
        g_w2lo[t2] = __float2bfloat16(x - __bfloat162float(hi));
    }
}

// ---------------- pipelined mma.sync bf16-split GEMM ---------------------------
// C[M,256] = A[M,K] @ B^T + bias. A bf16 hi/lo [M,K]; B bf16 hi/lo [256,K].
// CTA 128x128, 8 warps 4(M)x2(N), K-chunk 32, 2-stage cp.async pipeline.
// 3 fragment passes: hi*hi + hi*lo + lo*hi.
#define APAD 40                 // bf16 row stride in smem (80B)
#define BUFE (128*APAD)         // elements per operand buffer
#define STAGEE (4*BUFE)         // elements per pipeline stage

__global__ void __launch_bounds__(256, 2) k_gemm_mma(
    const __nv_bfloat16* __restrict__ Ahi, const __nv_bfloat16* __restrict__ Alo,
    const __nv_bfloat16* __restrict__ Bhi, const __nv_bfloat16* __restrict__ Blo,
    const float* __restrict__ bias, float* __restrict__ C,
    int M, int K,
    long long strideB, long long strideBias, long long strideC)
{
    extern __shared__ __nv_bfloat16 sm[];
    Bhi  += (size_t)blockIdx.z * strideB;
    Blo  += (size_t)blockIdx.z * strideB;
    bias += (size_t)blockIdx.z * strideBias;
    C    += (size_t)blockIdx.z * strideC;

    int tid = threadIdx.x, wid = tid >> 5, lane = tid & 31;
    int g = lane >> 2, tg = lane & 3;
    int row0 = blockIdx.x * 128, col0 = blockIdx.y * 128;
    int wm = (wid & 3) * 32;       // warp M offset in tile
    int wn = (wid >> 2) * 64;      // warp N offset in tile

    float acc[2][8][4];
    #pragma unroll
    for (int i = 0; i < 2; i++)
        #pragma unroll
        for (int j = 0; j < 8; j++)
            #pragma unroll
            for (int q = 0; q < 4; q++) acc[i][j][q] = 0.f;

    int nch = K >> 5;

    auto issue = [&](int c, int st) {
        int gk0 = c << 5;
        __nv_bfloat16* base = sm + st*STAGEE;
        #pragma unroll
        for (int it = 0; it < 2; it++) {
            int idx = it*256 + tid;
            int rr = idx >> 2, cq = (idx & 3) << 3;
            int so = rr*APAD + cq;
            int gr = row0 + rr;
            int va = (gr < M) ? 16 : 0;
            const __nv_bfloat16* pa  = (gr < M) ? (Ahi + (size_t)gr*K + gk0 + cq) : Ahi;
            const __nv_bfloat16* pal = (gr < M) ? (Alo + (size_t)gr*K + gk0 + cq) : Alo;
            cp16(smaddr(base + so),          pa,  va);
            cp16(smaddr(base + BUFE + so),   pal, va);
            size_t gb = (size_t)(col0 + rr)*K + gk0 + cq;   // B rows always in-range
            cp16(smaddr(base + 2*BUFE + so), Bhi + gb, 16);
            cp16(smaddr(base + 3*BUFE + so), Blo + gb, 16);
        }
        asm volatile("cp.async.commit_group;" ::: "memory");
    };

    issue(0, 0);
    for (int c = 0; c < nch; c++) {
        int st = c & 1;
        if (c + 1 < nch) {
            issue(c + 1, (c + 1) & 1);
            asm volatile("cp.async.wait_group 1;" ::: "memory");
        } else {
            asm volatile("cp.async.wait_group 0;" ::: "memory");
        }
        __syncthreads();

        const __nv_bfloat16* Ah_s = sm + st*STAGEE;
        const __nv_bfloat16* Al_s = Ah_s + BUFE;
        const __nv_bfloat16* Bh_s = Ah_s + 2*BUFE;
        const __nv_bfloat16* Bl_s = Ah_s + 3*BUFE;

        #pragma unroll
        for (int ks = 0; ks < 2; ks++) {
            int k0 = (ks << 4) + tg*2;
            uint32_t Ahf[2][4], Alf[2][4];
            #pragma unroll
            for (int i = 0; i < 2; i++) {
                int rb = wm + i*16 + g;
                Ahf[i][0] = *(const uint32_t*)&Ah_s[rb*APAD + k0];
                Ahf[i][1] = *(const uint32_t*)&Ah_s[(rb+8)*APAD + k0];
                Ahf[i][2] = *(const uint32_t*)&Ah_s[rb*APAD + k0 + 8];
                Ahf[i][3] = *(const uint32_t*)&Ah_s[(rb+8)*APAD + k0 + 8];
                Alf[i][0] = *(const uint32_t*)&Al_s[rb*APAD + k0];
                Alf[i][1] = *(const uint32_t*)&Al_s[(rb+8)*APAD + k0];
                Alf[i][2] = *(const uint32_t*)&Al_s[rb*APAD + k0 + 8];
                Alf[i][3] = *(const uint32_t*)&Al_s[(rb+8)*APAD + k0 + 8];
            }
            #pragma unroll
            for (int j = 0; j < 8; j++) {
                int nb = wn + j*8 + g;
                uint32_t Bhf[2], Blf[2];
                Bhf[0] = *(const uint32_t*)&Bh_s[nb*APAD + k0];
                Bhf[1] = *(const uint32_t*)&Bh_s[nb*APAD + k0 + 8];
                Blf[0] = *(const uint32_t*)&Bl_s[nb*APAD + k0];
                Blf[1] = *(const uint32_t*)&Bl_s[nb*APAD + k0 + 8];
                #pragma unroll
                for (int i = 0; i < 2; i++) {
                    mma16816(acc[i][j], Ahf[i], Bhf);
                    mma16816(acc[i][j], Ahf[i], Blf);
                    mma16816(acc[i][j], Alf[i], Bhf);
                }
            }
        }
        __syncthreads();
    }

    // epilogue
    #pragma unroll
    for (int i = 0; i < 2; i++) {
        int r0r = row0 + wm + i*16 + g;
        #pragma unroll
        for (int j = 0; j < 8; j++) {
            int cc = col0 + wn + j*8 + tg*2;
            float b0 = bias[cc], b1 = bias[cc+1];
            if (r0r < M) {
                float2 o = make_float2(acc[i][j][0] + b0, acc[i][j][1] + b1);
                *(float2*)(C + (size_t)r0r*HD + cc) = o;
            }
            if (r0r + 8 < M) {
                float2 o = make_float2(acc[i][j][2] + b0, acc[i][j][3] + b1);
                *(float2*)(C + (size_t)(r0r+8)*HD + cc) = o;
            }
        }
    }
}

// ---------------- edge aggregation: one warp per (node, relation) ----------------
__global__ void k_edge() {
    int r = blockIdx.y;
    int warp = threadIdx.x >> 5, lane = threadIdx.x & 31;
    int n = blockIdx.x*8 + warp;
    int idx = r*NN + n;
    float acc[8];
    #pragma unroll
    for (int k = 0; k < 8; k++) acc[k] = 0.f;

    int deg = g_counts[idx];
    if (deg > 0) {
        int base = g_rowptr[idx];
        float p2 = g_P2[n] + g_cscore;
        float4 q2 = *(const float4*)&g_Q2[idx*AHD];

        // pass 1: softmax denominators (4 heads)
        float d0 = 0.f, d1 = 0.f, d2 = 0.f, d3 = 0.f;
        for (int j = lane; j < deg; j += 32) {
            int s = g_srclist[base + j];
            float sc = g_P1[s] + p2;
            float sg = (sc > 0.f) ? 1.f : ((sc < 0.f) ? -1.f : 0.f);
            float4 q1 = *(const float4*)&g_Q1[(r*NN + s)*AHD];
            float a0 = sg*q1.x + q2.x; a0 = (a0 >= 0.f) ? a0 : 0.01f*a0;
            float a1 = sg*q1.y + q2.y; a1 = (a1 >= 0.f) ? a1 : 0.01f*a1;
            float a2 = sg*q1.z + q2.z; a2 = (a2 >= 0.f) ? a2 : 0.01f*a2;
            float a3 = sg*q1.w + q2.w; a3 = (a3 >= 0.f) ? a3 : 0.01f*a3;
            d0 += expf(a0); d1 += expf(a1); d2 += expf(a2); d3 += expf(a3);
        }
        #pragma unroll
        for (int o = 16; o; o >>= 1) {
            d0 += __shfl_xor_sync(0xffffffffu, d0, o);
            d1 += __shfl_xor_sync(0xffffffffu, d1, o);
            d2 += __shfl_xor_sync(0xffffffffu, d2, o);
            d3 += __shfl_xor_sync(0xffffffffu, d3, o);
        }
        float i0 = 1.f/d0, i1 = 1.f/d1, i2 = 1.f/d2, i3 = 1.f/d3;

        // pass 2: weighted feature gather/accumulate
        const float* hwr = g_hw + (size_t)r*NN*HD;
        int hl = lane >> 3;
        for (int c0 = 0; c0 < deg; c0 += 32) {
            int j = c0 + lane;
            int s = 0;
            float w0 = 0.f, w1 = 0.f, w2 = 0.f, w3 = 0.f;
            if (j < deg) {
                s = g_srclist[base + j];
                float sc = g_P1[s] + p2;
                float sg = (sc > 0.f) ? 1.f : ((sc < 0.f) ? -1.f : 0.f);
                float4 q1 = *(const float4*)&g_Q1[(r*NN + s)*AHD];
                float a0 = sg*q1.x + q2.x; a0 = (a0 >= 0.f) ? a0 : 0.01f*a0;
                float a1 = sg*q1.y + q2.y; a1 = (a1 >= 0.f) ? a1 : 0.01f*a1;
                float a2 = sg*q1.z + q2.z; a2 = (a2 >= 0.f) ? a2 : 0.01f*a2;
                float a3 = sg*q1.w + q2.w; a3 = (a3 >= 0.f) ? a3 : 0.01f*a3;
                w0 = sg * expf(a0) * i0;
                w1 = sg * expf(a1) * i1;
                w2 = sg * expf(a2) * i2;
                w3 = sg * expf(a3) * i3;
            }
            int m = min(32, deg - c0);
            for (int jj = 0; jj < m; jj++) {
                int   sbn = __shfl_sync(0xffffffffu, s,  jj);
                float t0 = __shfl_sync(0xffffffffu, w0, jj);
                float t1 = __shfl_sync(0xffffffffu, w1, jj);
                float t2 = __shfl_sync(0xffffffffu, w2, jj);
                float t3 = __shfl_sync(0xffffffffu, w3, jj);
                float wh = (hl == 0) ? t0 : ((hl == 1) ? t1 : ((hl == 2) ? t2 : t3));
                const float4* pp = (const float4*)(hwr + (size_t)sbn*HD + lane*8);
                float4 x0 = pp[0], x1 = pp[1];
                acc[0] += wh*x0.x; acc[1] += wh*x0.y; acc[2] += wh*x0.z; acc[3] += wh*x0.w;
                acc[4] += wh*x1.x; acc[5] += wh*x1.y; acc[6] += wh*x1.z; acc[7] += wh*x1.w;
            }
        }
    }
    // write bf16 hi/lo split directly (feeds GEMM2 A operand)
    __nv_bfloat16 hi[8], lo[8];
    #pragma unroll
    for (int k = 0; k < 8; k++) {
        hi[k] = __float2bfloat16(acc[k]);
        lo[k] = __float2bfloat16(acc[k] - __bfloat162float(hi[k]));
    }
    size_t ofs = (size_t)n*(RRD*HD) + r*HD + lane*8;
    *(uint4*)(g_a2hi + ofs) = *(uint4*)hi;
    *(uint4*)(g_a2lo + ofs) = *(uint4*)lo;
}

// ---------------- launch ----------------
extern "C" void kernel_launch(void* const* d_in, const int* in_sizes, int n_in,
                              void* d_out, int out_size) {
    const float* h    = (const float*)d_in[0];
    const float* dW   = (const float*)d_in[1];
    const float* db   = (const float*)d_in[2];
    const float* fW   = (const float*)d_in[3];
    const float* fb   = (const float*)d_in[4];
    const float* wW   = (const float*)d_in[5];
    const float* wb   = (const float*)d_in[6];
    const float* aW   = (const float*)d_in[7];
    const float* ab   = (const float*)d_in[8];
    const float* linW = (const float*)d_in[9];
    const float* linb = (const float*)d_in[10];
    const int*   src  = (const int*)d_in[11];
    const int*   dst  = (const int*)d_in[12];
    float* out = (float*)d_out;

    float *hwp = nullptr;
    __nv_bfloat16 *hhi, *hlo, *a2hi, *a2lo, *w1hi, *w1lo, *w2hi, *w2lo;
    cudaGetSymbolAddress((void**)&hwp,  g_hw);
    cudaGetSymbolAddress((void**)&hhi,  g_hhi);
    cudaGetSymbolAddress((void**)&hlo,  g_hlo);
    cudaGetSymbolAddress((void**)&a2hi, g_a2hi);
    cudaGetSymbolAddress((void**)&a2lo, g_a2lo);
    cudaGetSymbolAddress((void**)&w1hi, g_w1hi);
    cudaGetSymbolAddress((void**)&w1lo, g_w1lo);
    cudaGetSymbolAddress((void**)&w2hi, g_w2hi);
    cudaGetSymbolAddress((void**)&w2lo, g_w2lo);

    const int smem_bytes = 2*STAGEE*sizeof(__nv_bfloat16);   // 81920
    cudaFuncSetAttribute(k_gemm_mma, cudaFuncAttributeMaxDynamicSharedMemorySize, smem_bytes);

    // Launch order puts GEMM1 at index 3 (the slot ncu's -s setting captures).
    k_vecs<<<1, 128>>>(dW, db, fW, fb, wW, wb, aW, ab);
    k_split_h<<<(NN*IND/4 + 255)/256, 256>>>(h);
    k_transB<<<(RRD*HD*IND + HD*RRD*HD + 255)/256, 256>>>(wW, linW);

    // GEMM1: hw[r] = h @ wW[r] + wb[r]   (M=50000, K=128, N=256, z over relations)
    dim3 g1((NN + 127)/128, 2, RRD);
    k_gemm_mma<<<g1, 256, smem_bytes>>>(hhi, hlo, w1hi, w1lo, wb, hwp,
                                        NN, IND,
                                        (long long)HD*IND, (long long)HD,
                                        (long long)NN*HD);

    k_node<<<NN/8, 256>>>(h);
    k_zero<<<(RN + 255)/256, 256>>>();
    k_hist<<<(RE + 255)/256, 256>>>(dst);
    k_scan1<<<NB, 1024>>>();
    k_scan2<<<1, 256>>>();
    k_scan3<<<NB, 1024>>>();
    k_scatter<<<(RE + 255)/256, 256>>>(src, dst);

    dim3 g2(NN/8, RRD);
    k_edge<<<g2, 256>>>();

    // GEMM2: out = a2 @ linW + linb      (M=50000, K=768, N=256)
    dim3 g3((NN + 127)/128, 2, 1);
    k_gemm_mma<<<g3, 256, smem_bytes>>>(a2hi, a2lo, w2hi, w2lo, linb, out,
                                        NN, RRD*HD, 0, 0, 0);
}

// round 5
// speedup vs baseline: 2.0166x; 1.1433x over previous
#include <cuda_runtime.h>
#include <cuda_fp16.h>
#include <math.h>
#include <stdint.h>

#define NN 50000
#define EE 300000
#define IND 128
#define HFD 64
#define AHD 4
#define RRD 3
#define HD 256          // HF*AH
#define RN (RRD*NN)
#define RE (RRD*EE)
#define NB ((RN+1023)/1024)   // scan blocks = 147

// ---------------- scratch (device globals; no allocation) ----------------
__device__ __align__(16) __half g_hw16[(size_t)RRD*NN*HD];      // 76.8 MB fp16
__device__ __align__(16) __half g_hhi[(size_t)NN*IND];          // h split fp16
__device__ __align__(16) __half g_hlo[(size_t)NN*IND];
__device__ __align__(16) __half g_a2hi[(size_t)NN*RRD*HD];      // edge-out split
__device__ __align__(16) __half g_a2lo[(size_t)NN*RRD*HD];
__device__ __align__(16) __half g_w1h[RRD*HD*IND];              // wW^T  [R,256,128] fp16
__device__ __align__(16) __half g_w2h[HD*RRD*HD];               // linW^T [256,768] fp16
__device__ int   g_counts[RN];
__device__ int   g_rowptr[RN];
__device__ int   g_cursor[RN];
__device__ int   g_srclist[RE];
__device__ __align__(16) float g_P1[NN];
__device__ __align__(16) float g_P2[NN];
__device__ __align__(16) float g_Q1[RN*AHD];
__device__ __align__(16) float g_Q2[RN*AHD];
__device__ __align__(16) float g_u1[IND];
__device__ __align__(16) float g_u2[IND];
__device__ __align__(16) float g_v1[RRD*AHD*IND];
__device__ __align__(16) float g_v2[RRD*AHD*IND];
__device__ float g_cq1[RRD*AHD];
__device__ float g_cq2[RRD*AHD];
__device__ float g_cscore;
__device__ int   g_bsums[256];

// ---------------- helpers ----------------
__device__ __forceinline__ float warpdot(float h0, float h1, float h2, float h3,
                                         const float* __restrict__ v, int lane) {
    float s = h0*v[lane] + h1*v[lane+32] + h2*v[lane+64] + h3*v[lane+96];
    #pragma unroll
    for (int o = 16; o; o >>= 1) s += __shfl_xor_sync(0xffffffffu, s, o);
    return s;
}

__device__ __forceinline__ uint32_t smaddr(const void* p) {
    uint32_t a;
    asm("{ .reg .u64 t; cvta.to.shared.u64 t, %1; cvt.u32.u64 %0, t; }" : "=r"(a) : "l"(p));
    return a;
}
__device__ __forceinline__ void cp16(uint32_t d, const void* s, int sz) {
    asm volatile("cp.async.cg.shared.global [%0], [%1], 16, %2;" :: "r"(d), "l"(s), "r"(sz));
}

// mma.sync m16n8k16 fp16, fp32 accumulate (in-place)
__device__ __forceinline__ void mma16816(float* c, const uint32_t* a, const uint32_t* b) {
    asm volatile("mma.sync.aligned.m16n8k16.row.col.f32.f16.f16.f32 "
                 "{%0,%1,%2,%3}, {%4,%5,%6,%7}, {%8,%9}, {%0,%1,%2,%3};"
                 : "+f"(c[0]), "+f"(c[1]), "+f"(c[2]), "+f"(c[3])
                 : "r"(a[0]), "r"(a[1]), "r"(a[2]), "r"(a[3]), "r"(b[0]), "r"(b[1]));
}

// ---------------- CSR construction ----------------
__global__ void k_zero() {
    int i = blockIdx.x*blockDim.x + threadIdx.x;
    if (i < RN) { g_counts[i] = 0; g_cursor[i] = 0; }
}
__global__ void k_hist(const int* __restrict__ dst) {
    int t = blockIdx.x*blockDim.x + threadIdx.x;
    if (t < RE) {
        int r = t / EE;
        atomicAdd(&g_counts[r*NN + dst[t]], 1);
    }
}
__global__ void k_scan1() {
    __shared__ int sm[1024];
    int tid = threadIdx.x;
    int i = blockIdx.x*1024 + tid;
    int v = (i < RN) ? g_counts[i] : 0;
    sm[tid] = v; __syncthreads();
    for (int off = 1; off < 1024; off <<= 1) {
        int t = (tid >= off) ? sm[tid-off] : 0;
        __syncthreads();
        sm[tid] += t; __syncthreads();
    }
    if (i < RN) g_rowptr[i] = sm[tid] - v;
    if (tid == 1023) g_bsums[blockIdx.x] = sm[1023];
}
__global__ void k_scan2() {
    __shared__ int sm[256];
    int tid = threadIdx.x;
    int v = (tid < NB) ? g_bsums[tid] : 0;
    sm[tid] = v; __syncthreads();
    for (int off = 1; off < 256; off <<= 1) {
        int t = (tid >= off) ? sm[tid-off] : 0;
        __syncthreads();
        sm[tid] += t; __syncthreads();
    }
    if (tid < NB) g_bsums[tid] = sm[tid] - v;
}
__global__ void k_scan3() {
    int i = blockIdx.x*1024 + threadIdx.x;
    if (i < RN) g_rowptr[i] += g_bsums[blockIdx.x];
}
__global__ void k_scatter(const int* __restrict__ src, const int* __restrict__ dst) {
    int t = blockIdx.x*blockDim.x + threadIdx.x;
    if (t < RE) {
        int r = t / EE;
        int i = r*NN + dst[t];
        int pos = g_rowptr[i] + atomicAdd(&g_cursor[i], 1);
        g_srclist[pos] = src[t];
    }
}

// ---------------- small projection vectors ----------------
__global__ void k_vecs(const float* __restrict__ dW, const float* __restrict__ db,
                       const float* __restrict__ fW, const float* __restrict__ fb,
                       const float* __restrict__ wW, const float* __restrict__ wb,
                       const float* __restrict__ aW, const float* __restrict__ ab) {
    int i = threadIdx.x;  // 0..127
    float u1 = 0.f, u2 = 0.f;
    for (int j = 0; j < HD; j++) {
        float d  = dW[i*HD + j];
        float f0 = fW[j], f1 = fW[HD + j], f2 = fW[2*HD + j];
        u1 += d * (f0 + f2);
        u2 += d * (f1 - f2);
    }
    g_u1[i] = u1; g_u2[i] = u2;
    for (int r = 0; r < RRD; r++) {
        const float* a1 = aW + r*2*HFD;
        const float* a2 = a1 + HFD;
        for (int a = 0; a < AHD; a++) {
            const float* wp = wW + ((size_t)(r*IND + i))*HD + a*HFD;
            float v1 = 0.f, v2 = 0.f;
            for (int k = 0; k < HFD; k++) { v1 += wp[k]*a1[k]; v2 += wp[k]*a2[k]; }
            g_v1[(r*AHD + a)*IND + i] = v1;
            g_v2[(r*AHD + a)*IND + i] = v2;
        }
    }
    if (i == 0) {
        float c = fb[0];
        for (int j = 0; j < HD; j++) c += db[j] * (fW[j] + fW[HD + j]);
        g_cscore = c;
    }
    if (i < RRD*AHD) {
        int r = i / AHD, a = i % AHD;
        const float* wbp = wb + r*HD + a*HFD;
        const float* a1 = aW + r*2*HFD;
        const float* a2 = a1 + HFD;
        float c1 = 0.f, c2 = 0.f;
        for (int k = 0; k < HFD; k++) { c1 += wbp[k]*a1[k]; c2 += wbp[k]*a2[k]; }
        g_cq1[i] = c1;
        g_cq2[i] = c2 + ab[r];
    }
}

// ---------------- per-node scalars (exact fp32; feeds sign()) ----------------
__global__ void k_node(const float* __restrict__ h) {
    int warp = threadIdx.x >> 5, lane = threadIdx.x & 31;
    int n = blockIdx.x*8 + warp;
    const float* hp = h + (size_t)n*IND;
    float h0 = hp[lane], h1 = hp[lane+32], h2 = hp[lane+64], h3 = hp[lane+96];
    float p1 = warpdot(h0, h1, h2, h3, g_u1, lane);
    float p2 = warpdot(h0, h1, h2, h3, g_u2, lane);
    if (lane == 0) { g_P1[n] = p1; g_P2[n] = p2; }
    for (int ra = 0; ra < RRD*AHD; ra++) {
        float q1 = warpdot(h0, h1, h2, h3, g_v1 + ra*IND, lane);
        float q2 = warpdot(h0, h1, h2, h3, g_v2 + ra*IND, lane);
        if (lane == 0) {
            int r = ra / AHD, a = ra % AHD;
            g_Q1[(r*NN + n)*AHD + a] = q1 + g_cq1[ra];
            g_Q2[(r*NN + n)*AHD + a] = q2 + g_cq2[ra];
        }
    }
}

// ---------------- operand prep: split h (fp16 pair), fp16 B matrices ------------
__global__ void k_split_h(const float* __restrict__ h) {
    int t = blockIdx.x*blockDim.x + threadIdx.x;   // over NN*IND/4
    if (t >= NN*IND/4) return;
    float4 v = *(const float4*)(h + (size_t)t*4);
    __half hi[4], lo[4];
    float x[4] = {v.x, v.y, v.z, v.w};
    #pragma unroll
    for (int k = 0; k < 4; k++) {
        hi[k] = __float2half_rn(x[k]);
        lo[k] = __float2half_rn(x[k] - __half2float(hi[k]));
    }
    *(uint2*)(g_hhi + (size_t)t*4) = *(uint2*)hi;
    *(uint2*)(g_hlo + (size_t)t*4) = *(uint2*)lo;
}

__global__ void k_transB(const float* __restrict__ wW, const float* __restrict__ linW) {
    int t = blockIdx.x*blockDim.x + threadIdx.x;
    const int W1 = RRD*HD*IND;      // 98304
    const int W2 = HD*RRD*HD;       // 196608
    if (t < W1) {
        int r = t / (HD*IND);
        int rem = t % (HD*IND);
        int n = rem / IND, k = rem % IND;
        g_w1h[t] = __float2half_rn(wW[((size_t)r*IND + k)*HD + n]);
    } else if (t < W1 + W2) {
        int t2 = t - W1;
        int n = t2 / (RRD*HD), k = t2 % (RRD*HD);
        g_w2h[t2] = __float2half_rn(linW[(size_t)k*HD + n]);
    }
}

// ---------------- pipelined mma.sync fp16 2-pass GEMM -------------------------
// C[M,256] = (Ahi+Alo)[M,K] @ B^T + bias. A fp16 hi/lo; B fp16 single [256,K].
// CTA 128x128, 8 warps 4(M)x2(N), K-chunk 32, 2-stage cp.async pipeline.
#define APAD 40                 // fp16 row stride in smem (80B)
#define BUFE (128*APAD)         // elements per operand buffer
#define STAGEE (3*BUFE)         // 3 buffers per stage: Ahi, Alo, B

__global__ void __launch_bounds__(256, 2) k_gemm_mma(
    const __half* __restrict__ Ahi, const __half* __restrict__ Alo,
    const __half* __restrict__ Bh,
    const float* __restrict__ bias, void* __restrict__ Cv,
    int M, int K, int out_fp16,
    long long strideB, long long strideBias, long long strideC)
{
    extern __shared__ __half sm[];
    Bh   += (size_t)blockIdx.z * strideB;
    bias += (size_t)blockIdx.z * strideBias;
    size_t cbase = (size_t)blockIdx.z * strideC;

    int tid = threadIdx.x, wid = tid >> 5, lane = tid & 31;
    int g = lane >> 2, tg = lane & 3;
    int row0 = blockIdx.x * 128, col0 = blockIdx.y * 128;
    int wm = (wid & 3) * 32;       // warp M offset
    int wn = (wid >> 2) * 64;      // warp N offset

    float acc[2][8][4];
    #pragma unroll
    for (int i = 0; i < 2; i++)
        #pragma unroll
        for (int j = 0; j < 8; j++)
            #pragma unroll
            for (int q = 0; q < 4; q++) acc[i][j][q] = 0.f;

    int nch = K >> 5;

    auto issue = [&](int c, int st) {
        int gk0 = c << 5;
        __half* base = sm + st*STAGEE;
        #pragma unroll
        for (int it = 0; it < 2; it++) {
            int idx = it*256 + tid;
            int rr = idx >> 2, cq = (idx & 3) << 3;
            int so = rr*APAD + cq;
            int gr = row0 + rr;
            int va = (gr < M) ? 16 : 0;
            const __half* pa  = (gr < M) ? (Ahi + (size_t)gr*K + gk0 + cq) : Ahi;
            const __half* pal = (gr < M) ? (Alo + (size_t)gr*K + gk0 + cq) : Alo;
            cp16(smaddr(base + so),          pa,  va);
            cp16(smaddr(base + BUFE + so),   pal, va);
            size_t gb = (size_t)(col0 + rr)*K + gk0 + cq;   // B rows always in-range
            cp16(smaddr(base + 2*BUFE + so), Bh + gb, 16);
        }
        asm volatile("cp.async.commit_group;" ::: "memory");
    };

    issue(0, 0);
    for (int c = 0; c < nch; c++) {
        int st = c & 1;
        if (c + 1 < nch) {
            issue(c + 1, (c + 1) & 1);
            asm volatile("cp.async.wait_group 1;" ::: "memory");
        } else {
            asm volatile("cp.async.wait_group 0;" ::: "memory");
        }
        __syncthreads();

        const __half* Ah_s = sm + st*STAGEE;
        const __half* Al_s = Ah_s + BUFE;
        const __half* B_s  = Ah_s + 2*BUFE;

        #pragma unroll
        for (int ks = 0; ks < 2; ks++) {
            int k0 = (ks << 4) + tg*2;
            uint32_t Ahf[2][4], Alf[2][4];
            #pragma unroll
            for (int i = 0; i < 2; i++) {
                int rb = wm + i*16 + g;
                Ahf[i][0] = *(const uint32_t*)&Ah_s[rb*APAD + k0];
                Ahf[i][1] = *(const uint32_t*)&Ah_s[(rb+8)*APAD + k0];
                Ahf[i][2] = *(const uint32_t*)&Ah_s[rb*APAD + k0 + 8];
                Ahf[i][3] = *(const uint32_t*)&Ah_s[(rb+8)*APAD + k0 + 8];
                Alf[i][0] = *(const uint32_t*)&Al_s[rb*APAD + k0];
                Alf[i][1] = *(const uint32_t*)&Al_s[(rb+8)*APAD + k0];
                Alf[i][2] = *(const uint32_t*)&Al_s[rb*APAD + k0 + 8];
                Alf[i][3] = *(const uint32_t*)&Al_s[(rb+8)*APAD + k0 + 8];
            }
            #pragma unroll
            for (int j = 0; j < 8; j++) {
                int nb = wn + j*8 + g;
                uint32_t Bf[2];
                Bf[0] = *(const uint32_t*)&B_s[nb*APAD + k0];
                Bf[1] = *(const uint32_t*)&B_s[nb*APAD + k0 + 8];
                #pragma unroll
                for (int i = 0; i < 2; i++) {
                    mma16816(acc[i][j], Ahf[i], Bf);
                    mma16816(acc[i][j], Alf[i], Bf);
                }
            }
        }
        __syncthreads();
    }

    // epilogue (fp32 or fp16 output)
    #pragma unroll
    for (int i = 0; i < 2; i++) {
        int r0r = row0 + wm + i*16 + g;
        #pragma unroll
        for (int j = 0; j < 8; j++) {
            int cc = col0 + wn + j*8 + tg*2;
            float b0 = bias[cc], b1 = bias[cc+1];
            float v00 = acc[i][j][0] + b0, v01 = acc[i][j][1] + b1;
            float v10 = acc[i][j][2] + b0, v11 = acc[i][j][3] + b1;
            if (out_fp16) {
                __half* Ch = (__half*)Cv;
                if (r0r < M)
                    *(__half2*)(Ch + cbase + (size_t)r0r*HD + cc) =
                        __floats2half2_rn(v00, v01);
                if (r0r + 8 < M)
                    *(__half2*)(Ch + cbase + (size_t)(r0r+8)*HD + cc) =
                        __floats2half2_rn(v10, v11);
            } else {
                float* Cf = (float*)Cv;
                if (r0r < M)
                    *(float2*)(Cf + cbase + (size_t)r0r*HD + cc) = make_float2(v00, v01);
                if (r0r + 8 < M)
                    *(float2*)(Cf + cbase + (size_t)(r0r+8)*HD + cc) = make_float2(v10, v11);
            }
        }
    }
}

// ---------------- edge aggregation: one warp per (node, relation) ----------------
__global__ void k_edge() {
    int r = blockIdx.y;
    int warp = threadIdx.x >> 5, lane = threadIdx.x & 31;
    int n = blockIdx.x*8 + warp;
    int idx = r*NN + n;
    float acc[8];
    #pragma unroll
    for (int k = 0; k < 8; k++) acc[k] = 0.f;

    int deg = g_counts[idx];
    if (deg > 0) {
        int base = g_rowptr[idx];
        float p2 = g_P2[n] + g_cscore;
        float4 q2 = *(const float4*)&g_Q2[idx*AHD];

        // pass 1: softmax denominators (4 heads)
        float d0 = 0.f, d1 = 0.f, d2 = 0.f, d3 = 0.f;
        for (int j = lane; j < deg; j += 32) {
            int s = g_srclist[base + j];
            float sc = g_P1[s] + p2;
            float sg = (sc > 0.f) ? 1.f : ((sc < 0.f) ? -1.f : 0.f);
            float4 q1 = *(const float4*)&g_Q1[(r*NN + s)*AHD];
            float a0 = sg*q1.x + q2.x; a0 = (a0 >= 0.f) ? a0 : 0.01f*a0;
            float a1 = sg*q1.y + q2.y; a1 = (a1 >= 0.f) ? a1 : 0.01f*a1;
            float a2 = sg*q1.z + q2.z; a2 = (a2 >= 0.f) ? a2 : 0.01f*a2;
            float a3 = sg*q1.w + q2.w; a3 = (a3 >= 0.f) ? a3 : 0.01f*a3;
            d0 += expf(a0); d1 += expf(a1); d2 += expf(a2); d3 += expf(a3);
        }
        #pragma unroll
        for (int o = 16; o; o >>= 1) {
            d0 += __shfl_xor_sync(0xffffffffu, d0, o);
            d1 += __shfl_xor_sync(0xffffffffu, d1, o);
            d2 += __shfl_xor_sync(0xffffffffu, d2, o);
            d3 += __shfl_xor_sync(0xffffffffu, d3, o);
        }
        float i0 = 1.f/d0, i1 = 1.f/d1, i2 = 1.f/d2, i3 = 1.f/d3;

        // pass 2: weighted feature gather/accumulate (fp16 rows, 512B/edge)
        const __half* hwr = g_hw16 + (size_t)r*NN*HD;
        int hl = lane >> 3;
        for (int c0 = 0; c0 < deg; c0 += 32) {
            int j = c0 + lane;
            int s = 0;
            float w0 = 0.f, w1 = 0.f, w2 = 0.f, w3 = 0.f;
            if (j < deg) {
                s = g_srclist[base + j];
                float sc = g_P1[s] + p2;
                float sg = (sc > 0.f) ? 1.f : ((sc < 0.f) ? -1.f : 0.f);
                float4 q1 = *(const float4*)&g_Q1[(r*NN + s)*AHD];
                float a0 = sg*q1.x + q2.x; a0 = (a0 >= 0.f) ? a0 : 0.01f*a0;
                float a1 = sg*q1.y + q2.y; a1 = (a1 >= 0.f) ? a1 : 0.01f*a1;
                float a2 = sg*q1.z + q2.z; a2 = (a2 >= 0.f) ? a2 : 0.01f*a2;
                float a3 = sg*q1.w + q2.w; a3 = (a3 >= 0.f) ? a3 : 0.01f*a3;
                w0 = sg * expf(a0) * i0;
                w1 = sg * expf(a1) * i1;
                w2 = sg * expf(a2) * i2;
                w3 = sg * expf(a3) * i3;
            }
            int m = min(32, deg - c0);
            for (int jj = 0; jj < m; jj++) {
                int   sbn = __shfl_sync(0xffffffffu, s,  jj);
                float t0 = __shfl_sync(0xffffffffu, w0, jj);
                float t1 = __shfl_sync(0xffffffffu, w1, jj);
                float t2 = __shfl_sync(0xffffffffu, w2, jj);
                float t3 = __shfl_sync(0xffffffffu, w3, jj);
                float wh = (hl == 0) ? t0 : ((hl == 1) ? t1 : ((hl == 2) ? t2 : t3));
                uint4 v = *(const uint4*)(hwr + (size_t)sbn*HD + lane*8);
                float2 x0 = __half22float2(*(__half2*)&v.x);
                float2 x1 = __half22float2(*(__half2*)&v.y);
                float2 x2 = __half22float2(*(__half2*)&v.z);
                float2 x3 = __half22float2(*(__half2*)&v.w);
                acc[0] += wh*x0.x; acc[1] += wh*x0.y; acc[2] += wh*x1.x; acc[3] += wh*x1.y;
                acc[4] += wh*x2.x; acc[5] += wh*x2.y; acc[6] += wh*x3.x; acc[7] += wh*x3.y;
            }
        }
    }
    // write fp16 hi/lo split (feeds GEMM2 A operand)
    __half hi[8], lo[8];
    #pragma unroll
    for (int k = 0; k < 8; k++) {
        hi[k] = __float2half_rn(acc[k]);
        lo[k] = __float2half_rn(acc[k] - __half2float(hi[k]));
    }
    size_t ofs = (size_t)n*(RRD*HD) + r*HD + lane*8;
    *(uint4*)(g_a2hi + ofs) = *(uint4*)hi;
    *(uint4*)(g_a2lo + ofs) = *(uint4*)lo;
}

// ---------------- launch ----------------
extern "C" void kernel_launch(void* const* d_in, const int* in_sizes, int n_in,
                              void* d_out, int out_size) {
    const float* h    = (const float*)d_in[0];
    const float* dW   = (const float*)d_in[1];
    const float* db   = (const float*)d_in[2];
    const float* fW   = (const float*)d_in[3];
    const float* fb   = (const float*)d_in[4];
    const float* wW   = (const float*)d_in[5];
    const float* wb   = (const float*)d_in[6];
    const float* aW   = (const float*)d_in[7];
    const float* ab   = (const float*)d_in[8];
    const float* linW = (const float*)d_in[9];
    const float* linb = (const float*)d_in[10];
    const int*   src  = (const int*)d_in[11];
    const int*   dst  = (const int*)d_in[12];

    __half *hw16, *hhi, *hlo, *a2hi, *a2lo, *w1h, *w2h;
    cudaGetSymbolAddress((void**)&hw16, g_hw16);
    cudaGetSymbolAddress((void**)&hhi,  g_hhi);
    cudaGetSymbolAddress((void**)&hlo,  g_hlo);
    cudaGetSymbolAddress((void**)&a2hi, g_a2hi);
    cudaGetSymbolAddress((void**)&a2lo, g_a2lo);
    cudaGetSymbolAddress((void**)&w1h,  g_w1h);
    cudaGetSymbolAddress((void**)&w2h,  g_w2h);

    const int smem_bytes = 2*STAGEE*sizeof(__half);   // 61440
    cudaFuncSetAttribute(k_gemm_mma, cudaFuncAttributeMaxDynamicSharedMemorySize, smem_bytes);

    // GEMM1 kept at launch index 3 (the slot ncu captures).
    k_vecs<<<1, 128>>>(dW, db, fW, fb, wW, wb, aW, ab);
    k_split_h<<<(NN*IND/4 + 255)/256, 256>>>(h);
    k_transB<<<(RRD*HD*IND + HD*RRD*HD + 255)/256, 256>>>(wW, linW);

    // GEMM1: hw[r] = h @ wW[r] + wb[r]  -> fp16 (M=50000, K=128, N=256, z=R)
    dim3 g1((NN + 127)/128, 2, RRD);
    k_gemm_mma<<<g1, 256, smem_bytes>>>(hhi, hlo, w1h, wb, hw16,
                                        NN, IND, 1,
                                        (long long)HD*IND, (long long)HD,
                                        (long long)NN*HD);

    k_node<<<NN/8, 256>>>(h);
    k_zero<<<(RN + 255)/256, 256>>>();
    k_hist<<<(RE + 255)/256, 256>>>(dst);
    k_scan1<<<NB, 1024>>>();
    k_scan2<<<1, 256>>>();
    k_scan3<<<NB, 1024>>>();
    k_scatter<<<(RE + 255)/256, 256>>>(src, dst);

    dim3 g2(NN/8, RRD);
    k_edge<<<g2, 256>>>();

    // GEMM2: out = a2 @ linW + linb -> fp32 (M=50000, K=768, N=256)
    dim3 g3((NN + 127)/128, 2, 1);
    k_gemm_mma<<<g3, 256, smem_bytes>>>(a2hi, a2lo, w2h, linb, d_out,
                                        NN, RRD*HD, 0, 0, 0, 0);
}

// round 6
// speedup vs baseline: 2.1861x; 1.0840x over previous
#include <cuda_runtime.h>
#include <cuda_fp16.h>
#include <math.h>
#include <stdint.h>

#define NN 50000
#define EE 300000
#define IND 128
#define HFD 64
#define AHD 4
#define RRD 3
#define HD 256          // HF*AH
#define RN (RRD*NN)
#define RE (RRD*EE)
#define NB ((RN+1023)/1024)   // scan blocks = 147

// ---------------- scratch (device globals; no allocation) ----------------
__device__ __align__(16) __half g_hw16[(size_t)RRD*NN*HD];      // 76.8 MB fp16
__device__ __align__(16) __half g_hhi[(size_t)NN*IND];          // h split fp16
__device__ __align__(16) __half g_hlo[(size_t)NN*IND];
__device__ __align__(16) __half g_a2hi[(size_t)NN*RRD*HD];      // edge-out split
__device__ __align__(16) __half g_a2lo[(size_t)NN*RRD*HD];
__device__ __align__(16) __half g_w1h[RRD*HD*IND];              // wW^T  [R,256,128] fp16
__device__ __align__(16) __half g_w2h[HD*RRD*HD];               // linW^T [256,768] fp16
__device__ __align__(16) float4 g_ew[RE];                       // per-edge sg*exp(alpha), 4 heads
__device__ int   g_counts[RN];
__device__ int   g_rowptr[RN];
__device__ int   g_cursor[RN];
__device__ int   g_srclist[RE];
__device__ __align__(16) float g_P1[NN];
__device__ __align__(16) float g_P2[NN];
__device__ __align__(16) float g_Q1[RN*AHD];
__device__ __align__(16) float g_Q2[RN*AHD];
__device__ __align__(16) float g_u1[IND];
__device__ __align__(16) float g_u2[IND];
__device__ __align__(16) float g_v1[RRD*AHD*IND];
__device__ __align__(16) float g_v2[RRD*AHD*IND];
__device__ float g_cq1[RRD*AHD];
__device__ float g_cq2[RRD*AHD];
__device__ float g_cscore;
__device__ int   g_bsums[256];

// ---------------- helpers ----------------
__device__ __forceinline__ float warpdot(float h0, float h1, float h2, float h3,
                                         const float* __restrict__ v, int lane) {
    float s = h0*v[lane] + h1*v[lane+32] + h2*v[lane+64] + h3*v[lane+96];
    #pragma unroll
    for (int o = 16; o; o >>= 1) s += __shfl_xor_sync(0xffffffffu, s, o);
    return s;
}

__device__ __forceinline__ uint32_t smaddr(const void* p) {
    uint32_t a;
    asm("{ .reg .u64 t; cvta.to.shared.u64 t, %1; cvt.u32.u64 %0, t; }" : "=r"(a) : "l"(p));
    return a;
}
__device__ __forceinline__ void cp16(uint32_t d, const void* s, int sz) {
    asm volatile("cp.async.cg.shared.global [%0], [%1], 16, %2;" :: "r"(d), "l"(s), "r"(sz));
}

// mma.sync m16n8k16 fp16, fp32 accumulate (in-place)
__device__ __forceinline__ void mma16816(float* c, const uint32_t* a, const uint32_t* b) {
    asm volatile("mma.sync.aligned.m16n8k16.row.col.f32.f16.f16.f32 "
                 "{%0,%1,%2,%3}, {%4,%5,%6,%7}, {%8,%9}, {%0,%1,%2,%3};"
                 : "+f"(c[0]), "+f"(c[1]), "+f"(c[2]), "+f"(c[3])
                 : "r"(a[0]), "r"(a[1]), "r"(a[2]), "r"(a[3]), "r"(b[0]), "r"(b[1]));
}

// ---------------- CSR construction ----------------
__global__ void k_zero() {
    int i = blockIdx.x*blockDim.x + threadIdx.x;
    if (i < RN) { g_counts[i] = 0; g_cursor[i] = 0; }
}
__global__ void k_hist(const int* __restrict__ dst) {
    int t = blockIdx.x*blockDim.x + threadIdx.x;
    if (t < RE) {
        int r = t / EE;
        atomicAdd(&g_counts[r*NN + dst[t]], 1);
    }
}
__global__ void k_scan1() {
    __shared__ int sm[1024];
    int tid = threadIdx.x;
    int i = blockIdx.x*1024 + tid;
    int v = (i < RN) ? g_counts[i] : 0;
    sm[tid] = v; __syncthreads();
    for (int off = 1; off < 1024; off <<= 1) {
        int t = (tid >= off) ? sm[tid-off] : 0;
        __syncthreads();
        sm[tid] += t; __syncthreads();
    }
    if (i < RN) g_rowptr[i] = sm[tid] - v;
    if (tid == 1023) g_bsums[blockIdx.x] = sm[1023];
}
__global__ void k_scan2() {
    __shared__ int sm[256];
    int tid = threadIdx.x;
    int v = (tid < NB) ? g_bsums[tid] : 0;
    sm[tid] = v; __syncthreads();
    for (int off = 1; off < 256; off <<= 1) {
        int t = (tid >= off) ? sm[tid-off] : 0;
        __syncthreads();
        sm[tid] += t; __syncthreads();
    }
    if (tid < NB) g_bsums[tid] = sm[tid] - v;
}
__global__ void k_scan3() {
    int i = blockIdx.x*1024 + threadIdx.x;
    if (i < RN) g_rowptr[i] += g_bsums[blockIdx.x];
}

// scatter + per-edge attention weights (sg * exp(leaky(sg*Q1[s]+Q2[d]))) in fp32
__global__ void k_scatter(const int* __restrict__ src, const int* __restrict__ dst) {
    int t = blockIdx.x*blockDim.x + threadIdx.x;
    if (t >= RE) return;
    int r = t / EE;
    int s = src[t], d = dst[t];
    int i = r*NN + d;
    int pos = g_rowptr[i] + atomicAdd(&g_cursor[i], 1);
    g_srclist[pos] = s;

    float sc = g_P1[s] + g_P2[d] + g_cscore;
    float sg = (sc > 0.f) ? 1.f : ((sc < 0.f) ? -1.f : 0.f);
    float4 q1 = *(const float4*)&g_Q1[(r*NN + s)*AHD];
    float4 q2 = *(const float4*)&g_Q2[i*AHD];
    float a0 = sg*q1.x + q2.x; a0 = (a0 >= 0.f) ? a0 : 0.01f*a0;
    float a1 = sg*q1.y + q2.y; a1 = (a1 >= 0.f) ? a1 : 0.01f*a1;
    float a2 = sg*q1.z + q2.z; a2 = (a2 >= 0.f) ? a2 : 0.01f*a2;
    float a3 = sg*q1.w + q2.w; a3 = (a3 >= 0.f) ? a3 : 0.01f*a3;
    g_ew[pos] = make_float4(sg*expf(a0), sg*expf(a1), sg*expf(a2), sg*expf(a3));
}

// ---------------- small projection vectors ----------------
__global__ void k_vecs(const float* __restrict__ dW, const float* __restrict__ db,
                       const float* __restrict__ fW, const float* __restrict__ fb,
                       const float* __restrict__ wW, const float* __restrict__ wb,
                       const float* __restrict__ aW, const float* __restrict__ ab) {
    int i = threadIdx.x;  // 0..127
    float u1 = 0.f, u2 = 0.f;
    for (int j = 0; j < HD; j++) {
        float d  = dW[i*HD + j];
        float f0 = fW[j], f1 = fW[HD + j], f2 = fW[2*HD + j];
        u1 += d * (f0 + f2);
        u2 += d * (f1 - f2);
    }
    g_u1[i] = u1; g_u2[i] = u2;
    for (int r = 0; r < RRD; r++) {
        const float* a1 = aW + r*2*HFD;
        const float* a2 = a1 + HFD;
        for (int a = 0; a < AHD; a++) {
            const float* wp = wW + ((size_t)(r*IND + i))*HD + a*HFD;
            float v1 = 0.f, v2 = 0.f;
            for (int k = 0; k < HFD; k++) { v1 += wp[k]*a1[k]; v2 += wp[k]*a2[k]; }
            g_v1[(r*AHD + a)*IND + i] = v1;
            g_v2[(r*AHD + a)*IND + i] = v2;
        }
    }
    if (i == 0) {
        float c = fb[0];
        for (int j = 0; j < HD; j++) c += db[j] * (fW[j] + fW[HD + j]);
        g_cscore = c;
    }
    if (i < RRD*AHD) {
        int r = i / AHD, a = i % AHD;
        const float* wbp = wb + r*HD + a*HFD;
        const float* a1 = aW + r*2*HFD;
        const float* a2 = a1 + HFD;
        float c1 = 0.f, c2 = 0.f;
        for (int k = 0; k < HFD; k++) { c1 += wbp[k]*a1[k]; c2 += wbp[k]*a2[k]; }
        g_cq1[i] = c1;
        g_cq2[i] = c2 + ab[r];
    }
}

// ---------------- per-node scalars (exact fp32; feeds sign()) ----------------
__global__ void k_node(const float* __restrict__ h) {
    int warp = threadIdx.x >> 5, lane = threadIdx.x & 31;
    int n = blockIdx.x*8 + warp;
    const float* hp = h + (size_t)n*IND;
    float h0 = hp[lane], h1 = hp[lane+32], h2 = hp[lane+64], h3 = hp[lane+96];
    float p1 = warpdot(h0, h1, h2, h3, g_u1, lane);
    float p2 = warpdot(h0, h1, h2, h3, g_u2, lane);
    if (lane == 0) { g_P1[n] = p1; g_P2[n] = p2; }
    for (int ra = 0; ra < RRD*AHD; ra++) {
        float q1 = warpdot(h0, h1, h2, h3, g_v1 + ra*IND, lane);
        float q2 = warpdot(h0, h1, h2, h3, g_v2 + ra*IND, lane);
        if (lane == 0) {
            int r = ra / AHD, a = ra % AHD;
            g_Q1[(r*NN + n)*AHD + a] = q1 + g_cq1[ra];
            g_Q2[(r*NN + n)*AHD + a] = q2 + g_cq2[ra];
        }
    }
}

// ---------------- operand prep: split h (fp16 pair), fp16 B matrices ------------
__global__ void k_split_h(const float* __restrict__ h) {
    int t = blockIdx.x*blockDim.x + threadIdx.x;   // over NN*IND/4
    if (t >= NN*IND/4) return;
    float4 v = *(const float4*)(h + (size_t)t*4);
    __half hi[4], lo[4];
    float x[4] = {v.x, v.y, v.z, v.w};
    #pragma unroll
    for (int k = 0; k < 4; k++) {
        hi[k] = __float2half_rn(x[k]);
        lo[k] = __float2half_rn(x[k] - __half2float(hi[k]));
    }
    *(uint2*)(g_hhi + (size_t)t*4) = *(uint2*)hi;
    *(uint2*)(g_hlo + (size_t)t*4) = *(uint2*)lo;
}

__global__ void k_transB(const float* __restrict__ wW, const float* __restrict__ linW) {
    int t = blockIdx.x*blockDim.x + threadIdx.x;
    const int W1 = RRD*HD*IND;      // 98304
    const int W2 = HD*RRD*HD;       // 196608
    if (t < W1) {
        int r = t / (HD*IND);
        int rem = t % (HD*IND);
        int n = rem / IND, k = rem % IND;
        g_w1h[t] = __float2half_rn(wW[((size_t)r*IND + k)*HD + n]);
    } else if (t < W1 + W2) {
        int t2 = t - W1;
        int n = t2 / (RRD*HD), k = t2 % (RRD*HD);
        g_w2h[t2] = __float2half_rn(linW[(size_t)k*HD + n]);
    }
}

// ---------------- pipelined mma.sync fp16 2-pass GEMM -------------------------
#define APAD 40                 // fp16 row stride in smem (80B)
#define BUFE (128*APAD)         // elements per operand buffer
#define STAGEE (3*BUFE)         // 3 buffers per stage: Ahi, Alo, B

__global__ void __launch_bounds__(256, 2) k_gemm_mma(
    const __half* __restrict__ Ahi, const __half* __restrict__ Alo,
    const __half* __restrict__ Bh,
    const float* __restrict__ bias, void* __restrict__ Cv,
    int M, int K, int out_fp16,
    long long strideB, long long strideBias, long long strideC)
{
    extern __shared__ __half sm[];
    Bh   += (size_t)blockIdx.z * strideB;
    bias += (size_t)blockIdx.z * strideBias;
    size_t cbase = (size_t)blockIdx.z * strideC;

    int tid = threadIdx.x, wid = tid >> 5, lane = tid & 31;
    int g = lane >> 2, tg = lane & 3;
    int row0 = blockIdx.x * 128, col0 = blockIdx.y * 128;
    int wm = (wid & 3) * 32;
    int wn = (wid >> 2) * 64;

    float acc[2][8][4];
    #pragma unroll
    for (int i = 0; i < 2; i++)
        #pragma unroll
        for (int j = 0; j < 8; j++)
            #pragma unroll
            for (int q = 0; q < 4; q++) acc[i][j][q] = 0.f;

    int nch = K >> 5;

    auto issue = [&](int c, int st) {
        int gk0 = c << 5;
        __half* base = sm + st*STAGEE;
        #pragma unroll
        for (int it = 0; it < 2; it++) {
            int idx = it*256 + tid;
            int rr = idx >> 2, cq = (idx & 3) << 3;
            int so = rr*APAD + cq;
            int gr = row0 + rr;
            int va = (gr < M) ? 16 : 0;
            const __half* pa  = (gr < M) ? (Ahi + (size_t)gr*K + gk0 + cq) : Ahi;
            const __half* pal = (gr < M) ? (Alo + (size_t)gr*K + gk0 + cq) : Alo;
            cp16(smaddr(base + so),          pa,  va);
            cp16(smaddr(base + BUFE + so),   pal, va);
            size_t gb = (size_t)(col0 + rr)*K + gk0 + cq;
            cp16(smaddr(base + 2*BUFE + so), Bh + gb, 16);
        }
        asm volatile("cp.async.commit_group;" ::: "memory");
    };

    issue(0, 0);
    for (int c = 0; c < nch; c++) {
        int st = c & 1;
        if (c + 1 < nch) {
            issue(c + 1, (c + 1) & 1);
            asm volatile("cp.async.wait_group 1;" ::: "memory");
        } else {
            asm volatile("cp.async.wait_group 0;" ::: "memory");
        }
        __syncthreads();

        const __half* Ah_s = sm + st*STAGEE;
        const __half* Al_s = Ah_s + BUFE;
        const __half* B_s  = Ah_s + 2*BUFE;

        #pragma unroll
        for (int ks = 0; ks < 2; ks++) {
            int k0 = (ks << 4) + tg*2;
            uint32_t Ahf[2][4], Alf[2][4];
            #pragma unroll
            for (int i = 0; i < 2; i++) {
                int rb = wm + i*16 + g;
                Ahf[i][0] = *(const uint32_t*)&Ah_s[rb*APAD + k0];
                Ahf[i][1] = *(const uint32_t*)&Ah_s[(rb+8)*APAD + k0];
                Ahf[i][2] = *(const uint32_t*)&Ah_s[rb*APAD + k0 + 8];
                Ahf[i][3] = *(const uint32_t*)&Ah_s[(rb+8)*APAD + k0 + 8];
                Alf[i][0] = *(const uint32_t*)&Al_s[rb*APAD + k0];
                Alf[i][1] = *(const uint32_t*)&Al_s[(rb+8)*APAD + k0];
                Alf[i][2] = *(const uint32_t*)&Al_s[rb*APAD + k0 + 8];
                Alf[i][3] = *(const uint32_t*)&Al_s[(rb+8)*APAD + k0 + 8];
            }
            #pragma unroll
            for (int j = 0; j < 8; j++) {
                int nb = wn + j*8 + g;
                uint32_t Bf[2];
                Bf[0] = *(const uint32_t*)&B_s[nb*APAD + k0];
                Bf[1] = *(const uint32_t*)&B_s[nb*APAD + k0 + 8];
                #pragma unroll
                for (int i = 0; i < 2; i++) {
                    mma16816(acc[i][j], Ahf[i], Bf);
                    mma16816(acc[i][j], Alf[i], Bf);
                }
            }
        }
        __syncthreads();
    }

    #pragma unroll
    for (int i = 0; i < 2; i++) {
        int r0r = row0 + wm + i*16 + g;
        #pragma unroll
        for (int j = 0; j < 8; j++) {
            int cc = col0 + wn + j*8 + tg*2;
            float b0 = bias[cc], b1 = bias[cc+1];
            float v00 = acc[i][j][0] + b0, v01 = acc[i][j][1] + b1;
            float v10 = acc[i][j][2] + b0, v11 = acc[i][j][3] + b1;
            if (out_fp16) {
                __half* Ch = (__half*)Cv;
                if (r0r < M)
                    *(__half2*)(Ch + cbase + (size_t)r0r*HD + cc) =
                        __floats2half2_rn(v00, v01);
                if (r0r + 8 < M)
                    *(__half2*)(Ch + cbase + (size_t)(r0r+8)*HD + cc) =
                        __floats2half2_rn(v10, v11);
            } else {
                float* Cf = (float*)Cv;
                if (r0r < M)
                    *(float2*)(Cf + cbase + (size_t)r0r*HD + cc) = make_float2(v00, v01);
                if (r0r + 8 < M)
                    *(float2*)(Cf + cbase + (size_t)(r0r+8)*HD + cc) = make_float2(v10, v11);
            }
        }
    }
}

// ---------------- edge aggregation: one warp per (node, relation) ----------------
// Weights precomputed in g_ew (fp32). Pass1: coalesced |ew| sums. Pass2: 4-deep
// unrolled gather of hw16 rows (MLP=4) with uniform broadcast weight loads.
__global__ void k_edge() {
    int r = blockIdx.y;
    int warp = threadIdx.x >> 5, lane = threadIdx.x & 31;
    int n = blockIdx.x*8 + warp;
    int idx = r*NN + n;
    float acc[8];
    #pragma unroll
    for (int k = 0; k < 8; k++) acc[k] = 0.f;

    int deg = g_counts[idx];
    if (deg > 0) {
        int base = g_rowptr[idx];

        // pass 1: denominators = sum |ew| per head (lane-strided, coalesced)
        float d0 = 0.f, d1 = 0.f, d2 = 0.f, d3 = 0.f;
        for (int j = lane; j < deg; j += 32) {
            float4 e = g_ew[base + j];
            d0 += fabsf(e.x); d1 += fabsf(e.y); d2 += fabsf(e.z); d3 += fabsf(e.w);
        }
        #pragma unroll
        for (int o = 16; o; o >>= 1) {
            d0 += __shfl_xor_sync(0xffffffffu, d0, o);
            d1 += __shfl_xor_sync(0xffffffffu, d1, o);
            d2 += __shfl_xor_sync(0xffffffffu, d2, o);
            d3 += __shfl_xor_sync(0xffffffffu, d3, o);
        }
        int hl = lane >> 3;
        float invh = 1.f / ((hl == 0) ? d0 : (hl == 1) ? d1 : (hl == 2) ? d2 : d3);

        const __half* hwr = g_hw16 + (size_t)r*NN*HD;
        const int*   sl = g_srclist + base;
        const float4* ew = g_ew + base;
        int co = lane*8;

        auto pick = [&](float4 e) -> float {
            return (hl == 0) ? e.x : (hl == 1) ? e.y : (hl == 2) ? e.z : e.w;
        };
        auto accum = [&](uint4 v, float wh) {
            float2 x0 = __half22float2(*(__half2*)&v.x);
            float2 x1 = __half22float2(*(__half2*)&v.y);
            float2 x2 = __half22float2(*(__half2*)&v.z);
            float2 x3 = __half22float2(*(__half2*)&v.w);
            acc[0] += wh*x0.x; acc[1] += wh*x0.y; acc[2] += wh*x1.x; acc[3] += wh*x1.y;
            acc[4] += wh*x2.x; acc[5] += wh*x2.y; acc[6] += wh*x3.x; acc[7] += wh*x3.y;
        };

        int j = 0;
        for (; j + 4 <= deg; j += 4) {
            int s0 = sl[j], s1 = sl[j+1], s2 = sl[j+2], s3 = sl[j+3];
            float4 e0 = ew[j], e1 = ew[j+1], e2 = ew[j+2], e3 = ew[j+3];
            uint4 v0 = *(const uint4*)(hwr + (size_t)s0*HD + co);
            uint4 v1 = *(const uint4*)(hwr + (size_t)s1*HD + co);
            uint4 v2 = *(const uint4*)(hwr + (size_t)s2*HD + co);
            uint4 v3 = *(const uint4*)(hwr + (size_t)s3*HD + co);
            accum(v0, pick(e0)*invh);
            accum(v1, pick(e1)*invh);
            accum(v2, pick(e2)*invh);
            accum(v3, pick(e3)*invh);
        }
        for (; j < deg; j++) {
            int s0 = sl[j];
            float4 e0 = ew[j];
            uint4 v0 = *(const uint4*)(hwr + (size_t)s0*HD + co);
            accum(v0, pick(e0)*invh);
        }
    }
    // write fp16 hi/lo split (feeds GEMM2 A operand)
    __half hi[8], lo[8];
    #pragma unroll
    for (int k = 0; k < 8; k++) {
        hi[k] = __float2half_rn(acc[k]);
        lo[k] = __float2half_rn(acc[k] - __half2float(hi[k]));
    }
    size_t ofs = (size_t)n*(RRD*HD) + r*HD + lane*8;
    *(uint4*)(g_a2hi + ofs) = *(uint4*)hi;
    *(uint4*)(g_a2lo + ofs) = *(uint4*)lo;
}

// ---------------- launch ----------------
extern "C" void kernel_launch(void* const* d_in, const int* in_sizes, int n_in,
                              void* d_out, int out_size) {
    const float* h    = (const float*)d_in[0];
    const float* dW   = (const float*)d_in[1];
    const float* db   = (const float*)d_in[2];
    const float* fW   = (const float*)d_in[3];
    const float* fb   = (const float*)d_in[4];
    const float* wW   = (const float*)d_in[5];
    const float* wb   = (const float*)d_in[6];
    const float* aW   = (const float*)d_in[7];
    const float* ab   = (const float*)d_in[8];
    const float* linW = (const float*)d_in[9];
    const float* linb = (const float*)d_in[10];
    const int*   src  = (const int*)d_in[11];
    const int*   dst  = (const int*)d_in[12];

    __half *hw16, *hhi, *hlo, *a2hi, *a2lo, *w1h, *w2h;
    cudaGetSymbolAddress((void**)&hw16, g_hw16);
    cudaGetSymbolAddress((void**)&hhi,  g_hhi);
    cudaGetSymbolAddress((void**)&hlo,  g_hlo);
    cudaGetSymbolAddress((void**)&a2hi, g_a2hi);
    cudaGetSymbolAddress((void**)&a2lo, g_a2lo);
    cudaGetSymbolAddress((void**)&w1h,  g_w1h);
    cudaGetSymbolAddress((void**)&w2h,  g_w2h);

    const int smem_bytes = 2*STAGEE*sizeof(__half);   // 61440
    cudaFuncSetAttribute(k_gemm_mma, cudaFuncAttributeMaxDynamicSharedMemorySize, smem_bytes);

    // GEMM1 kept at launch index 3 (the slot ncu captures).
    k_vecs<<<1, 128>>>(dW, db, fW, fb, wW, wb, aW, ab);
    k_split_h<<<(NN*IND/4 + 255)/256, 256>>>(h);
    k_transB<<<(RRD*HD*IND + HD*RRD*HD + 255)/256, 256>>>(wW, linW);

    // GEMM1: hw[r] = h @ wW[r] + wb[r]  -> fp16 (M=50000, K=128, N=256, z=R)
    dim3 g1((NN + 127)/128, 2, RRD);
    k_gemm_mma<<<g1, 256, smem_bytes>>>(hhi, hlo, w1h, wb, hw16,
                                        NN, IND, 1,
                                        (long long)HD*IND, (long long)HD,
                                        (long long)NN*HD);

    k_node<<<NN/8, 256>>>(h);
    k_zero<<<(RN + 255)/256, 256>>>();
    k_hist<<<(RE + 255)/256, 256>>>(dst);
    k_scan1<<<NB, 1024>>>();
    k_scan2<<<1, 256>>>();
    k_scan3<<<NB, 1024>>>();
    k_scatter<<<(RE + 255)/256, 256>>>(src, dst);

    dim3 g2(NN/8, RRD);
    k_edge<<<g2, 256>>>();

    // GEMM2: out = a2 @ linW + linb -> fp32 (M=50000, K=768, N=256)
    dim3 g3((NN + 127)/128, 2, 1);
    k_gemm_mma<<<g3, 256, smem_bytes>>>(a2hi, a2lo, w2h, linb, d_out,
                                        NN, RRD*HD, 0, 0, 0, 0);
}

// round 7
// speedup vs baseline: 2.5982x; 1.1885x over previous
#include <cuda_runtime.h>
#include <cuda_fp16.h>
#include <math.h>
#include <stdint.h>

#define NN 50000
#define EE 300000
#define IND 128
#define HFD 64
#define AHD 4
#define RRD 3
#define HD 256          // HF*AH
#define RN (RRD*NN)
#define RE (RRD*EE)
#define NB ((RN+1023)/1024)   // scan blocks = 147

// ---------------- scratch (device globals; no allocation) ----------------
__device__ __align__(16) __half g_hw16[(size_t)RRD*NN*HD];      // 76.8 MB fp16
__device__ __align__(16) __half g_hhi[(size_t)NN*IND];          // h fp16
__device__ __align__(16) __half g_a2hi[(size_t)NN*RRD*HD];      // edge-out fp16
__device__ __align__(16) __half g_w1h[RRD*HD*IND];              // wW^T  [R,256,128] fp16
__device__ __align__(16) __half g_w2h[HD*RRD*HD];               // linW^T [256,768] fp16
__device__ __align__(16) float4 g_ew[RE];                       // per-edge sg*exp(alpha), 4 heads
__device__ int   g_counts[RN];
__device__ int   g_rowptr[RN];
__device__ int   g_cursor[RN];
__device__ int   g_srclist[RE];
__device__ __align__(16) float g_P1[NN];
__device__ __align__(16) float g_P2[NN];
__device__ __align__(16) float g_Q1[RN*AHD];
__device__ __align__(16) float g_Q2[RN*AHD];
__device__ __align__(16) float g_u1[IND];
__device__ __align__(16) float g_u2[IND];
__device__ __align__(16) float g_v1[RRD*AHD*IND];
__device__ __align__(16) float g_v2[RRD*AHD*IND];
__device__ float g_cq1[RRD*AHD];
__device__ float g_cq2[RRD*AHD];
__device__ float g_cscore;
__device__ int   g_bsums[256];

// ---------------- helpers ----------------
__device__ __forceinline__ float warpdot(float h0, float h1, float h2, float h3,
                                         const float* __restrict__ v, int lane) {
    float s = h0*v[lane] + h1*v[lane+32] + h2*v[lane+64] + h3*v[lane+96];
    #pragma unroll
    for (int o = 16; o; o >>= 1) s += __shfl_xor_sync(0xffffffffu, s, o);
    return s;
}

__device__ __forceinline__ uint32_t smaddr(const void* p) {
    uint32_t a;
    asm("{ .reg .u64 t; cvta.to.shared.u64 t, %1; cvt.u32.u64 %0, t; }" : "=r"(a) : "l"(p));
    return a;
}
__device__ __forceinline__ void cp16(uint32_t d, const void* s, int sz) {
    asm volatile("cp.async.cg.shared.global [%0], [%1], 16, %2;" :: "r"(d), "l"(s), "r"(sz));
}

// mma.sync m16n8k16 fp16, fp32 accumulate (in-place)
__device__ __forceinline__ void mma16816(float* c, const uint32_t* a, const uint32_t* b) {
    asm volatile("mma.sync.aligned.m16n8k16.row.col.f32.f16.f16.f32 "
                 "{%0,%1,%2,%3}, {%4,%5,%6,%7}, {%8,%9}, {%0,%1,%2,%3};"
                 : "+f"(c[0]), "+f"(c[1]), "+f"(c[2]), "+f"(c[3])
                 : "r"(a[0]), "r"(a[1]), "r"(a[2]), "r"(a[3]), "r"(b[0]), "r"(b[1]));
}

// ---------------- CSR construction ----------------
__global__ void k_zero() {
    int i = blockIdx.x*blockDim.x + threadIdx.x;
    if (i < RN) { g_counts[i] = 0; g_cursor[i] = 0; }
}
__global__ void k_hist(const int* __restrict__ dst) {
    int t = blockIdx.x*blockDim.x + threadIdx.x;
    if (t < RE) {
        int r = t / EE;
        atomicAdd(&g_counts[r*NN + dst[t]], 1);
    }
}
__global__ void k_scan1() {
    __shared__ int sm[1024];
    int tid = threadIdx.x;
    int i = blockIdx.x*1024 + tid;
    int v = (i < RN) ? g_counts[i] : 0;
    sm[tid] = v; __syncthreads();
    for (int off = 1; off < 1024; off <<= 1) {
        int t = (tid >= off) ? sm[tid-off] : 0;
        __syncthreads();
        sm[tid] += t; __syncthreads();
    }
    if (i < RN) g_rowptr[i] = sm[tid] - v;
    if (tid == 1023) g_bsums[blockIdx.x] = sm[1023];
}
__global__ void k_scan2() {
    __shared__ int sm[256];
    int tid = threadIdx.x;
    int v = (tid < NB) ? g_bsums[tid] : 0;
    sm[tid] = v; __syncthreads();
    for (int off = 1; off < 256; off <<= 1) {
        int t = (tid >= off) ? sm[tid-off] : 0;
        __syncthreads();
        sm[tid] += t; __syncthreads();
    }
    if (tid < NB) g_bsums[tid] = sm[tid] - v;
}
__global__ void k_scan3() {
    int i = blockIdx.x*1024 + threadIdx.x;
    if (i < RN) g_rowptr[i] += g_bsums[blockIdx.x];
}

// scatter + per-edge attention weights (sg * exp(leaky(sg*Q1[s]+Q2[d]))) in fp32
__global__ void k_scatter(const int* __restrict__ src, const int* __restrict__ dst) {
    int t = blockIdx.x*blockDim.x + threadIdx.x;
    if (t >= RE) return;
    int r = t / EE;
    int s = src[t], d = dst[t];
    int i = r*NN + d;
    int pos = g_rowptr[i] + atomicAdd(&g_cursor[i], 1);
    g_srclist[pos] = s;

    float sc = g_P1[s] + g_P2[d] + g_cscore;
    float sg = (sc > 0.f) ? 1.f : ((sc < 0.f) ? -1.f : 0.f);
    float4 q1 = *(const float4*)&g_Q1[(r*NN + s)*AHD];
    float4 q2 = *(const float4*)&g_Q2[i*AHD];
    float a0 = sg*q1.x + q2.x; a0 = (a0 >= 0.f) ? a0 : 0.01f*a0;
    float a1 = sg*q1.y + q2.y; a1 = (a1 >= 0.f) ? a1 : 0.01f*a1;
    float a2 = sg*q1.z + q2.z; a2 = (a2 >= 0.f) ? a2 : 0.01f*a2;
    float a3 = sg*q1.w + q2.w; a3 = (a3 >= 0.f) ? a3 : 0.01f*a3;
    g_ew[pos] = make_float4(sg*expf(a0), sg*expf(a1), sg*expf(a2), sg*expf(a3));
}

// ---------------- small projection vectors ----------------
__global__ void k_vecs(const float* __restrict__ dW, const float* __restrict__ db,
                       const float* __restrict__ fW, const float* __restrict__ fb,
                       const float* __restrict__ wW, const float* __restrict__ wb,
                       const float* __restrict__ aW, const float* __restrict__ ab) {
    int i = threadIdx.x;  // 0..127
    float u1 = 0.f, u2 = 0.f;
    for (int j = 0; j < HD; j++) {
        float d  = dW[i*HD + j];
        float f0 = fW[j], f1 = fW[HD + j], f2 = fW[2*HD + j];
        u1 += d * (f0 + f2);
        u2 += d * (f1 - f2);
    }
    g_u1[i] = u1; g_u2[i] = u2;
    for (int r = 0; r < RRD; r++) {
        const float* a1 = aW + r*2*HFD;
        const float* a2 = a1 + HFD;
        for (int a = 0; a < AHD; a++) {
            const float* wp = wW + ((size_t)(r*IND + i))*HD + a*HFD;
            float v1 = 0.f, v2 = 0.f;
            for (int k = 0; k < HFD; k++) { v1 += wp[k]*a1[k]; v2 += wp[k]*a2[k]; }
            g_v1[(r*AHD + a)*IND + i] = v1;
            g_v2[(r*AHD + a)*IND + i] = v2;
        }
    }
    if (i == 0) {
        float c = fb[0];
        for (int j = 0; j < HD; j++) c += db[j] * (fW[j] + fW[HD + j]);
        g_cscore = c;
    }
    if (i < RRD*AHD) {
        int r = i / AHD, a = i % AHD;
        const float* wbp = wb + r*HD + a*HFD;
        const float* a1 = aW + r*2*HFD;
        const float* a2 = a1 + HFD;
        float c1 = 0.f, c2 = 0.f;
        for (int k = 0; k < HFD; k++) { c1 += wbp[k]*a1[k]; c2 += wbp[k]*a2[k]; }
        g_cq1[i] = c1;
        g_cq2[i] = c2 + ab[r];
    }
}

// ---------------- per-node scalars (exact fp32; feeds sign()) ----------------
__global__ void k_node(const float* __restrict__ h) {
    int warp = threadIdx.x >> 5, lane = threadIdx.x & 31;
    int n = blockIdx.x*8 + warp;
    const float* hp = h + (size_t)n*IND;
    float h0 = hp[lane], h1 = hp[lane+32], h2 = hp[lane+64], h3 = hp[lane+96];
    float p1 = warpdot(h0, h1, h2, h3, g_u1, lane);
    float p2 = warpdot(h0, h1, h2, h3, g_u2, lane);
    if (lane == 0) { g_P1[n] = p1; g_P2[n] = p2; }
    for (int ra = 0; ra < RRD*AHD; ra++) {
        float q1 = warpdot(h0, h1, h2, h3, g_v1 + ra*IND, lane);
        float q2 = warpdot(h0, h1, h2, h3, g_v2 + ra*IND, lane);
        if (lane == 0) {
            int r = ra / AHD, a = ra % AHD;
            g_Q1[(r*NN + n)*AHD + a] = q1 + g_cq1[ra];
            g_Q2[(r*NN + n)*AHD + a] = q2 + g_cq2[ra];
        }
    }
}

// ---------------- operand prep: fp16 casts ----------------
__global__ void k_split_h(const float* __restrict__ h) {
    int t = blockIdx.x*blockDim.x + threadIdx.x;   // over NN*IND/4
    if (t >= NN*IND/4) return;
    float4 v = *(const float4*)(h + (size_t)t*4);
    __half hi[4];
    hi[0] = __float2half_rn(v.x); hi[1] = __float2half_rn(v.y);
    hi[2] = __float2half_rn(v.z); hi[3] = __float2half_rn(v.w);
    *(uint2*)(g_hhi + (size_t)t*4) = *(uint2*)hi;
}

__global__ void k_transB(const float* __restrict__ wW, const float* __restrict__ linW) {
    int t = blockIdx.x*blockDim.x + threadIdx.x;
    const int W1 = RRD*HD*IND;      // 98304
    const int W2 = HD*RRD*HD;       // 196608
    if (t < W1) {
        int r = t / (HD*IND);
        int rem = t % (HD*IND);
        int n = rem / IND, k = rem % IND;
        g_w1h[t] = __float2half_rn(wW[((size_t)r*IND + k)*HD + n]);
    } else if (t < W1 + W2) {
        int t2 = t - W1;
        int n = t2 / (RRD*HD), k = t2 % (RRD*HD);
        g_w2h[t2] = __float2half_rn(linW[(size_t)k*HD + n]);
    }
}

// ---------------- 3-stage pipelined mma.sync fp16 GEMM ------------------------
// C[M,256] = A[M,K] @ B^T + bias. A,B fp16. CTA 128x128, 8 warps 4(M)x2(N),
// K-chunk 32, 3-stage cp.async pipeline.
#define APAD 40                 // fp16 row stride in smem (80B)
#define BUFE (128*APAD)         // elements per operand buffer
#define STAGEE (2*BUFE)         // 2 buffers per stage: A, B

__global__ void __launch_bounds__(256, 2) k_gemm_mma(
    const __half* __restrict__ Ah, const __half* __restrict__ Bh,
    const float* __restrict__ bias, void* __restrict__ Cv,
    int M, int K, int out_fp16,
    long long strideB, long long strideBias, long long strideC)
{
    extern __shared__ __half sm[];
    Bh   += (size_t)blockIdx.z * strideB;
    bias += (size_t)blockIdx.z * strideBias;
    size_t cbase = (size_t)blockIdx.z * strideC;

    int tid = threadIdx.x, wid = tid >> 5, lane = tid & 31;
    int g = lane >> 2, tg = lane & 3;
    int row0 = blockIdx.x * 128, col0 = blockIdx.y * 128;
    int wm = (wid & 3) * 32;
    int wn = (wid >> 2) * 64;

    float acc[2][8][4];
    #pragma unroll
    for (int i = 0; i < 2; i++)
        #pragma unroll
        for (int j = 0; j < 8; j++)
            #pragma unroll
            for (int q = 0; q < 4; q++) acc[i][j][q] = 0.f;

    int nch = K >> 5;

    auto issue = [&](int c, int st) {
        int gk0 = c << 5;
        __half* base = sm + st*STAGEE;
        #pragma unroll
        for (int it = 0; it < 2; it++) {
            int idx = it*256 + tid;
            int rr = idx >> 2, cq = (idx & 3) << 3;
            int so = rr*APAD + cq;
            int gr = row0 + rr;
            int va = (gr < M) ? 16 : 0;
            const __half* pa = (gr < M) ? (Ah + (size_t)gr*K + gk0 + cq) : Ah;
            cp16(smaddr(base + so), pa, va);
            size_t gb = (size_t)(col0 + rr)*K + gk0 + cq;   // B rows always in-range
            cp16(smaddr(base + BUFE + so), Bh + gb, 16);
        }
        asm volatile("cp.async.commit_group;" ::: "memory");
    };

    issue(0, 0);
    if (nch > 1) issue(1, 1);
    for (int c = 0; c < nch; c++) {
        int st = c % 3;
        if (c + 2 < nch) {
            issue(c + 2, (c + 2) % 3);
            asm volatile("cp.async.wait_group 2;" ::: "memory");
        } else if (c + 1 < nch) {
            asm volatile("cp.async.wait_group 1;" ::: "memory");
        } else {
            asm volatile("cp.async.wait_group 0;" ::: "memory");
        }
        __syncthreads();

        const __half* A_s = sm + st*STAGEE;
        const __half* B_s = A_s + BUFE;

        #pragma unroll
        for (int ks = 0; ks < 2; ks++) {
            int k0 = (ks << 4) + tg*2;
            uint32_t Af[2][4];
            #pragma unroll
            for (int i = 0; i < 2; i++) {
                int rb = wm + i*16 + g;
                Af[i][0] = *(const uint32_t*)&A_s[rb*APAD + k0];
                Af[i][1] = *(const uint32_t*)&A_s[(rb+8)*APAD + k0];
                Af[i][2] = *(const uint32_t*)&A_s[rb*APAD + k0 + 8];
                Af[i][3] = *(const uint32_t*)&A_s[(rb+8)*APAD + k0 + 8];
            }
            #pragma unroll
            for (int j = 0; j < 8; j++) {
                int nb = wn + j*8 + g;
                uint32_t Bf[2];
                Bf[0] = *(const uint32_t*)&B_s[nb*APAD + k0];
                Bf[1] = *(const uint32_t*)&B_s[nb*APAD + k0 + 8];
                mma16816(acc[0][j], Af[0], Bf);
                mma16816(acc[1][j], Af[1], Bf);
            }
        }
        __syncthreads();
    }

    #pragma unroll
    for (int i = 0; i < 2; i++) {
        int r0r = row0 + wm + i*16 + g;
        #pragma unroll
        for (int j = 0; j < 8; j++) {
            int cc = col0 + wn + j*8 + tg*2;
            float b0 = bias[cc], b1 = bias[cc+1];
            float v00 = acc[i][j][0] + b0, v01 = acc[i][j][1] + b1;
            float v10 = acc[i][j][2] + b0, v11 = acc[i][j][3] + b1;
            if (out_fp16) {
                __half* Ch = (__half*)Cv;
                if (r0r < M)
                    *(__half2*)(Ch + cbase + (size_t)r0r*HD + cc) =
                        __floats2half2_rn(v00, v01);
                if (r0r + 8 < M)
                    *(__half2*)(Ch + cbase + (size_t)(r0r+8)*HD + cc) =
                        __floats2half2_rn(v10, v11);
            } else {
                float* Cf = (float*)Cv;
                if (r0r < M)
                    *(float2*)(Cf + cbase + (size_t)r0r*HD + cc) = make_float2(v00, v01);
                if (r0r + 8 < M)
                    *(float2*)(Cf + cbase + (size_t)(r0r+8)*HD + cc) = make_float2(v10, v11);
            }
        }
    }
}

// ---------------- edge aggregation: one warp per (node, relation) ----------------
__global__ void k_edge() {
    int r = blockIdx.y;
    int warp = threadIdx.x >> 5, lane = threadIdx.x & 31;
    int n = blockIdx.x*8 + warp;
    int idx = r*NN + n;
    float acc[8];
    #pragma unroll
    for (int k = 0; k < 8; k++) acc[k] = 0.f;

    int deg = g_counts[idx];
    if (deg > 0) {
        int base = g_rowptr[idx];

        // pass 1: denominators = sum |ew| per head (lane-strided, coalesced)
        float d0 = 0.f, d1 = 0.f, d2 = 0.f, d3 = 0.f;
        for (int j = lane; j < deg; j += 32) {
            float4 e = g_ew[base + j];
            d0 += fabsf(e.x); d1 += fabsf(e.y); d2 += fabsf(e.z); d3 += fabsf(e.w);
        }
        #pragma unroll
        for (int o = 16; o; o >>= 1) {
            d0 += __shfl_xor_sync(0xffffffffu, d0, o);
            d1 += __shfl_xor_sync(0xffffffffu, d1, o);
            d2 += __shfl_xor_sync(0xffffffffu, d2, o);
            d3 += __shfl_xor_sync(0xffffffffu, d3, o);
        }
        int hl = lane >> 3;
        float invh = 1.f / ((hl == 0) ? d0 : (hl == 1) ? d1 : (hl == 2) ? d2 : d3);

        const __half* hwr = g_hw16 + (size_t)r*NN*HD;
        const int*   sl = g_srclist + base;
        const float4* ew = g_ew + base;
        int co = lane*8;

        auto pick = [&](float4 e) -> float {
            return (hl == 0) ? e.x : (hl == 1) ? e.y : (hl == 2) ? e.z : e.w;
        };
        auto accum = [&](uint4 v, float wh) {
            float2 x0 = __half22float2(*(__half2*)&v.x);
            float2 x1 = __half22float2(*(__half2*)&v.y);
            float2 x2 = __half22float2(*(__half2*)&v.z);
            float2 x3 = __half22float2(*(__half2*)&v.w);
            acc[0] += wh*x0.x; acc[1] += wh*x0.y; acc[2] += wh*x1.x; acc[3] += wh*x1.y;
            acc[4] += wh*x2.x; acc[5] += wh*x2.y; acc[6] += wh*x3.x; acc[7] += wh*x3.y;
        };

        int j = 0;
        for (; j + 4 <= deg; j += 4) {
            int s0 = sl[j], s1 = sl[j+1], s2 = sl[j+2], s3 = sl[j+3];
            float4 e0 = ew[j], e1 = ew[j+1], e2 = ew[j+2], e3 = ew[j+3];
            uint4 v0 = *(const uint4*)(hwr + (size_t)s0*HD + co);
            uint4 v1 = *(const uint4*)(hwr + (size_t)s1*HD + co);
            uint4 v2 = *(const uint4*)(hwr + (size_t)s2*HD + co);
            uint4 v3 = *(const uint4*)(hwr + (size_t)s3*HD + co);
            accum(v0, pick(e0)*invh);
            accum(v1, pick(e1)*invh);
            accum(v2, pick(e2)*invh);
            accum(v3, pick(e3)*invh);
        }
        for (; j < deg; j++) {
            int s0 = sl[j];
            float4 e0 = ew[j];
            uint4 v0 = *(const uint4*)(hwr + (size_t)s0*HD + co);
            accum(v0, pick(e0)*invh);
        }
    }
    // write fp16 (feeds GEMM2 A operand)
    __half hi[8];
    #pragma unroll
    for (int k = 0; k < 8; k++) hi[k] = __float2half_rn(acc[k]);
    size_t ofs = (size_t)n*(RRD*HD) + r*HD + lane*8;
    *(uint4*)(g_a2hi + ofs) = *(uint4*)hi;
}

// ---------------- launch ----------------
extern "C" void kernel_launch(void* const* d_in, const int* in_sizes, int n_in,
                              void* d_out, int out_size) {
    const float* h    = (const float*)d_in[0];
    const float* dW   = (const float*)d_in[1];
    const float* db   = (const float*)d_in[2];
    const float* fW   = (const float*)d_in[3];
    const float* fb   = (const float*)d_in[4];
    const float* wW   = (const float*)d_in[5];
    const float* wb   = (const float*)d_in[6];
    const float* aW   = (const float*)d_in[7];
    const float* ab   = (const float*)d_in[8];
    const float* linW = (const float*)d_in[9];
    const float* linb = (const float*)d_in[10];
    const int*   src  = (const int*)d_in[11];
    const int*   dst  = (const int*)d_in[12];

    __half *hw16, *hhi, *a2hi, *w1h, *w2h;
    cudaGetSymbolAddress((void**)&hw16, g_hw16);
    cudaGetSymbolAddress((void**)&hhi,  g_hhi);
    cudaGetSymbolAddress((void**)&a2hi, g_a2hi);
    cudaGetSymbolAddress((void**)&w1h,  g_w1h);
    cudaGetSymbolAddress((void**)&w2h,  g_w2h);

    const int smem_bytes = 3*STAGEE*sizeof(__half);   // 61440
    cudaFuncSetAttribute(k_gemm_mma, cudaFuncAttributeMaxDynamicSharedMemorySize, smem_bytes);

    // GEMM1 kept at launch index 3 (the slot ncu captures).
    k_vecs<<<1, 128>>>(dW, db, fW, fb, wW, wb, aW, ab);
    k_split_h<<<(NN*IND/4 + 255)/256, 256>>>(h);
    k_transB<<<(RRD*HD*IND + HD*RRD*HD + 255)/256, 256>>>(wW, linW);

    // GEMM1: hw[r] = h @ wW[r] + wb[r]  -> fp16 (M=50000, K=128, N=256, z=R)
    dim3 g1((NN + 127)/128, 2, RRD);
    k_gemm_mma<<<g1, 256, smem_bytes>>>(hhi, w1h, wb, hw16,
                                        NN, IND, 1,
                                        (long long)HD*IND, (long long)HD,
                                        (long long)NN*HD);

    k_node<<<NN/8, 256>>>(h);
    k_zero<<<(RN + 255)/256, 256>>>();
    k_hist<<<(RE + 255)/256, 256>>>(dst);
    k_scan1<<<NB, 1024>>>();
    k_scan2<<<1, 256>>>();
    k_scan3<<<NB, 1024>>>();
    k_scatter<<<(RE + 255)/256, 256>>>(src, dst);

    dim3 g2(NN/8, RRD);
    k_edge<<<g2, 256>>>();

    // GEMM2: out = a2 @ linW + linb -> fp32 (M=50000, K=768, N=256)
    dim3 g3((NN + 127)/128, 2, 1);
    k_gemm_mma<<<g3, 256, smem_bytes>>>(a2hi, w2h, linb, d_out,
                                        NN, RRD*HD, 0, 0, 0, 0);
}

// round 8
// speedup vs baseline: 2.6879x; 1.0345x over previous
#include <cuda_runtime.h>
#include <cuda_fp16.h>
#include <math.h>
#include <stdint.h>

#define NN 50000
#define EE 300000
#define IND 128
#define HFD 64
#define AHD 4
#define RRD 3
#define HD 256          // HF*AH
#define RN (RRD*NN)
#define RE (RRD*EE)
#define NB ((RN+1023)/1024)   // scan blocks = 147

// ---------------- scratch (device globals; no allocation) ----------------
__device__ __align__(16) __half g_hw16[(size_t)RRD*NN*HD];      // 76.8 MB fp16
__device__ __align__(16) __half g_hhi[(size_t)NN*IND];          // h fp16
__device__ __align__(16) __half g_a2hi[(size_t)NN*RRD*HD];      // edge-out fp16
__device__ __align__(16) __half g_w1h[RRD*HD*IND];              // wW^T  [R,256,128] fp16
__device__ __align__(16) __half g_w2h[HD*RRD*HD];               // linW^T [256,768] fp16
__device__ __align__(16) float4 g_ew[RE];                       // per-edge sg*exp(alpha), 4 heads
__device__ int   g_counts[RN];
__device__ int   g_rowptr[RN];
__device__ int   g_cursor[RN];
__device__ int   g_srclist[RE];
__device__ __align__(16) float g_P1[NN];
__device__ __align__(16) float g_P2[NN];
__device__ __align__(16) float g_Q1[RN*AHD];
__device__ __align__(16) float g_Q2[RN*AHD];
__device__ __align__(16) float g_u1[IND];
__device__ __align__(16) float g_u2[IND];
__device__ __align__(16) float g_v1[RRD*AHD*IND];
__device__ __align__(16) float g_v2[RRD*AHD*IND];
__device__ float g_cq1[RRD*AHD];
__device__ float g_cq2[RRD*AHD];
__device__ float g_cscore;
__device__ int   g_bsums[256];

// ---------------- helpers ----------------
__device__ __forceinline__ float warpdot(float h0, float h1, float h2, float h3,
                                         const float* __restrict__ v, int lane) {
    float s = h0*v[lane] + h1*v[lane+32] + h2*v[lane+64] + h3*v[lane+96];
    #pragma unroll
    for (int o = 16; o; o >>= 1) s += __shfl_xor_sync(0xffffffffu, s, o);
    return s;
}

__device__ __forceinline__ uint32_t smaddr(const void* p) {
    uint32_t a;
    asm("{ .reg .u64 t; cvta.to.shared.u64 t, %1; cvt.u32.u64 %0, t; }" : "=r"(a) : "l"(p));
    return a;
}
__device__ __forceinline__ void cp16(uint32_t d, const void* s, int sz) {
    asm volatile("cp.async.cg.shared.global [%0], [%1], 16, %2;" :: "r"(d), "l"(s), "r"(sz));
}
__device__ __forceinline__ void ldsm4(uint32_t* r, uint32_t addr) {
    asm volatile("ldmatrix.sync.aligned.m8n8.x4.shared.b16 {%0,%1,%2,%3}, [%4];"
                 : "=r"(r[0]), "=r"(r[1]), "=r"(r[2]), "=r"(r[3]) : "r"(addr));
}

// mma.sync m16n8k16 fp16, fp32 accumulate (in-place)
__device__ __forceinline__ void mma16816(float* c, const uint32_t* a, uint32_t b0, uint32_t b1) {
    asm volatile("mma.sync.aligned.m16n8k16.row.col.f32.f16.f16.f32 "
                 "{%0,%1,%2,%3}, {%4,%5,%6,%7}, {%8,%9}, {%0,%1,%2,%3};"
                 : "+f"(c[0]), "+f"(c[1]), "+f"(c[2]), "+f"(c[3])
                 : "r"(a[0]), "r"(a[1]), "r"(a[2]), "r"(a[3]), "r"(b0), "r"(b1));
}

// ---------------- CSR construction ----------------
__global__ void k_zero() {
    int i = blockIdx.x*blockDim.x + threadIdx.x;
    if (i < RN) { g_counts[i] = 0; g_cursor[i] = 0; }
}
__global__ void k_hist(const int* __restrict__ dst) {
    int t = blockIdx.x*blockDim.x + threadIdx.x;
    if (t < RE) {
        int r = t / EE;
        atomicAdd(&g_counts[r*NN + dst[t]], 1);
    }
}
__global__ void k_scan1() {
    __shared__ int sm[1024];
    int tid = threadIdx.x;
    int i = blockIdx.x*1024 + tid;
    int v = (i < RN) ? g_counts[i] : 0;
    sm[tid] = v; __syncthreads();
    for (int off = 1; off < 1024; off <<= 1) {
        int t = (tid >= off) ? sm[tid-off] : 0;
        __syncthreads();
        sm[tid] += t; __syncthreads();
    }
    if (i < RN) g_rowptr[i] = sm[tid] - v;
    if (tid == 1023) g_bsums[blockIdx.x] = sm[1023];
}
__global__ void k_scan2() {
    __shared__ int sm[256];
    int tid = threadIdx.x;
    int v = (tid < NB) ? g_bsums[tid] : 0;
    sm[tid] = v; __syncthreads();
    for (int off = 1; off < 256; off <<= 1) {
        int t = (tid >= off) ? sm[tid-off] : 0;
        __syncthreads();
        sm[tid] += t; __syncthreads();
    }
    if (tid < NB) g_bsums[tid] = sm[tid] - v;
}
__global__ void k_scan3() {
    int i = blockIdx.x*1024 + threadIdx.x;
    if (i < RN) g_rowptr[i] += g_bsums[blockIdx.x];
}

// scatter + per-edge attention weights (sg * exp(leaky(sg*Q1[s]+Q2[d]))) in fp32
__global__ void k_scatter(const int* __restrict__ src, const int* __restrict__ dst) {
    int t = blockIdx.x*blockDim.x + threadIdx.x;
    if (t >= RE) return;
    int r = t / EE;
    int s = src[t], d = dst[t];
    int i = r*NN + d;
    int pos = g_rowptr[i] + atomicAdd(&g_cursor[i], 1);
    g_srclist[pos] = s;

    float sc = g_P1[s] + g_P2[d] + g_cscore;
    float sg = (sc > 0.f) ? 1.f : ((sc < 0.f) ? -1.f : 0.f);
    float4 q1 = *(const float4*)&g_Q1[(r*NN + s)*AHD];
    float4 q2 = *(const float4*)&g_Q2[i*AHD];
    float a0 = sg*q1.x + q2.x; a0 = (a0 >= 0.f) ? a0 : 0.01f*a0;
    float a1 = sg*q1.y + q2.y; a1 = (a1 >= 0.f) ? a1 : 0.01f*a1;
    float a2 = sg*q1.z + q2.z; a2 = (a2 >= 0.f) ? a2 : 0.01f*a2;
    float a3 = sg*q1.w + q2.w; a3 = (a3 >= 0.f) ? a3 : 0.01f*a3;
    g_ew[pos] = make_float4(sg*expf(a0), sg*expf(a1), sg*expf(a2), sg*expf(a3));
}

// ---------------- small projection vectors ----------------
__global__ void k_vecs(const float* __restrict__ dW, const float* __restrict__ db,
                       const float* __restrict__ fW, const float* __restrict__ fb,
                       const float* __restrict__ wW, const float* __restrict__ wb,
                       const float* __restrict__ aW, const float* __restrict__ ab) {
    int i = threadIdx.x;  // 0..127
    float u1 = 0.f, u2 = 0.f;
    for (int j = 0; j < HD; j++) {
        float d  = dW[i*HD + j];
        float f0 = fW[j], f1 = fW[HD + j], f2 = fW[2*HD + j];
        u1 += d * (f0 + f2);
        u2 += d * (f1 - f2);
    }
    g_u1[i] = u1; g_u2[i] = u2;
    for (int r = 0; r < RRD; r++) {
        const float* a1 = aW + r*2*HFD;
        const float* a2 = a1 + HFD;
        for (int a = 0; a < AHD; a++) {
            const float* wp = wW + ((size_t)(r*IND + i))*HD + a*HFD;
            float v1 = 0.f, v2 = 0.f;
            for (int k = 0; k < HFD; k++) { v1 += wp[k]*a1[k]; v2 += wp[k]*a2[k]; }
            g_v1[(r*AHD + a)*IND + i] = v1;
            g_v2[(r*AHD + a)*IND + i] = v2;
        }
    }
    if (i == 0) {
        float c = fb[0];
        for (int j = 0; j < HD; j++) c += db[j] * (fW[j] + fW[HD + j]);
        g_cscore = c;
    }
    if (i < RRD*AHD) {
        int r = i / AHD, a = i % AHD;
        const float* wbp = wb + r*HD + a*HFD;
        const float* a1 = aW + r*2*HFD;
        const float* a2 = a1 + HFD;
        float c1 = 0.f, c2 = 0.f;
        for (int k = 0; k < HFD; k++) { c1 += wbp[k]*a1[k]; c2 += wbp[k]*a2[k]; }
        g_cq1[i] = c1;
        g_cq2[i] = c2 + ab[r];
    }
}

// ---------------- per-node scalars (exact fp32) + fp16 h emit ------------------
__global__ void k_node(const float* __restrict__ h) {
    int warp = threadIdx.x >> 5, lane = threadIdx.x & 31;
    int n = blockIdx.x*8 + warp;
    const float* hp = h + (size_t)n*IND;
    float h0 = hp[lane], h1 = hp[lane+32], h2 = hp[lane+64], h3 = hp[lane+96];
    // fp16 copy of h (fused former k_split_h)
    __half* hh = g_hhi + (size_t)n*IND;
    hh[lane]      = __float2half_rn(h0);
    hh[lane + 32] = __float2half_rn(h1);
    hh[lane + 64] = __float2half_rn(h2);
    hh[lane + 96] = __float2half_rn(h3);

    float p1 = warpdot(h0, h1, h2, h3, g_u1, lane);
    float p2 = warpdot(h0, h1, h2, h3, g_u2, lane);
    if (lane == 0) { g_P1[n] = p1; g_P2[n] = p2; }
    for (int ra = 0; ra < RRD*AHD; ra++) {
        float q1 = warpdot(h0, h1, h2, h3, g_v1 + ra*IND, lane);
        float q2 = warpdot(h0, h1, h2, h3, g_v2 + ra*IND, lane);
        if (lane == 0) {
            int r = ra / AHD, a = ra % AHD;
            g_Q1[(r*NN + n)*AHD + a] = q1 + g_cq1[ra];
            g_Q2[(r*NN + n)*AHD + a] = q2 + g_cq2[ra];
        }
    }
}

// ---------------- operand prep: fp16 weight transposes ----------------
__global__ void k_transB(const float* __restrict__ wW, const float* __restrict__ linW) {
    int t = blockIdx.x*blockDim.x + threadIdx.x;
    const int W1 = RRD*HD*IND;      // 98304
    const int W2 = HD*RRD*HD;       // 196608
    if (t < W1) {
        int r = t / (HD*IND);
        int rem = t % (HD*IND);
        int n = rem / IND, k = rem % IND;
        g_w1h[t] = __float2half_rn(wW[((size_t)r*IND + k)*HD + n]);
    } else if (t < W1 + W2) {
        int t2 = t - W1;
        int n = t2 / (RRD*HD), k = t2 % (RRD*HD);
        g_w2h[t2] = __float2half_rn(linW[(size_t)k*HD + n]);
    }
}

// ---------------- 3-stage pipelined mma.sync fp16 GEMM (ldmatrix frags) --------
// C[M,256] = A[M,K] @ B^T + bias. A,B fp16. CTA 128x128, 8 warps 4(M)x2(N),
// K-chunk 32, 3-stage cp.async pipeline, ldmatrix.x4 fragment loads.
#define APAD 40                 // fp16 row stride in smem (80B)
#define BUFE (128*APAD)         // elements per operand buffer
#define STAGEE (2*BUFE)         // 2 buffers per stage: A, B

__global__ void __launch_bounds__(256, 2) k_gemm_mma(
    const __half* __restrict__ Ah, const __half* __restrict__ Bh,
    const float* __restrict__ bias, void* __restrict__ Cv,
    int M, int K, int out_fp16,
    long long strideB, long long strideBias, long long strideC)
{
    extern __shared__ __half sm[];
    Bh   += (size_t)blockIdx.z * strideB;
    bias += (size_t)blockIdx.z * strideBias;
    size_t cbase = (size_t)blockIdx.z * strideC;

    int tid = threadIdx.x, wid = tid >> 5, lane = tid & 31;
    int g = lane >> 2, tg = lane & 3;
    int row0 = blockIdx.x * 128, col0 = blockIdx.y * 128;
    int wm = (wid & 3) * 32;
    int wn = (wid >> 2) * 64;

    // ldmatrix per-lane address offsets (bytes)
    int rowa = (lane & 7) + ((lane >> 3) & 1) * 8;   // A: m0/m1 rows, m2/m3 cols+8
    int cola = (lane >> 4) * 8;
    int rowb = (lane & 7) + (lane >> 4) * 8;         // B: m0/m1 k-halves, m2/m3 rows+8
    int colb = ((lane >> 3) & 1) * 8;
    uint32_t smb = smaddr(sm);
    uint32_t aoff = ((wm + rowa)*APAD + cola) * 2;
    uint32_t boff = BUFE*2 + ((wn + rowb)*APAD + colb) * 2;

    float acc[2][8][4];
    #pragma unroll
    for (int i = 0; i < 2; i++)
        #pragma unroll
        for (int j = 0; j < 8; j++)
            #pragma unroll
            for (int q = 0; q < 4; q++) acc[i][j][q] = 0.f;

    int nch = K >> 5;

    auto issue = [&](int c, int st) {
        int gk0 = c << 5;
        __half* base = sm + st*STAGEE;
        #pragma unroll
        for (int it = 0; it < 2; it++) {
            int idx = it*256 + tid;
            int rr = idx >> 2, cq = (idx & 3) << 3;
            int so = rr*APAD + cq;
            int gr = row0 + rr;
            int va = (gr < M) ? 16 : 0;
            const __half* pa = (gr < M) ? (Ah + (size_t)gr*K + gk0 + cq) : Ah;
            cp16(smaddr(base + so), pa, va);
            size_t gb = (size_t)(col0 + rr)*K + gk0 + cq;   // B rows always in-range
            cp16(smaddr(base + BUFE + so), Bh + gb, 16);
        }
        asm volatile("cp.async.commit_group;" ::: "memory");
    };

    issue(0, 0);
    if (nch > 1) issue(1, 1);
    for (int c = 0; c < nch; c++) {
        int st = c % 3;
        if (c + 2 < nch) {
            issue(c + 2, (c + 2) % 3);
            asm volatile("cp.async.wait_group 2;" ::: "memory");
        } else if (c + 1 < nch) {
            asm volatile("cp.async.wait_group 1;" ::: "memory");
        } else {
            asm volatile("cp.async.wait_group 0;" ::: "memory");
        }
        __syncthreads();

        uint32_t stb = smb + st*(STAGEE*2);
        #pragma unroll
        for (int ks = 0; ks < 2; ks++) {
            uint32_t kb = ks * 32;    // 16 fp16 = 32 bytes
            uint32_t Af[2][4], Bq[4][4];
            ldsm4(Af[0], stb + aoff + kb);
            ldsm4(Af[1], stb + aoff + 16*APAD*2 + kb);
            #pragma unroll
            for (int jp = 0; jp < 4; jp++)
                ldsm4(Bq[jp], stb + boff + jp*(16*APAD*2) + kb);
            #pragma unroll
            for (int j = 0; j < 8; j++) {
                uint32_t b0 = Bq[j >> 1][(j & 1) * 2];
                uint32_t b1 = Bq[j >> 1][(j & 1) * 2 + 1];
                mma16816(acc[0][j], Af[0], b0, b1);
                mma16816(acc[1][j], Af[1], b0, b1);
            }
        }
        __syncthreads();
    }

    #pragma unroll
    for (int i = 0; i < 2; i++) {
        int r0r = row0 + wm + i*16 + g;
        #pragma unroll
        for (int j = 0; j < 8; j++) {
            int cc = col0 + wn + j*8 + tg*2;
            float b0 = bias[cc], b1 = bias[cc+1];
            float v00 = acc[i][j][0] + b0, v01 = acc[i][j][1] + b1;
            float v10 = acc[i][j][2] + b0, v11 = acc[i][j][3] + b1;
            if (out_fp16) {
                __half* Ch = (__half*)Cv;
                if (r0r < M)
                    *(__half2*)(Ch + cbase + (size_t)r0r*HD + cc) =
                        __floats2half2_rn(v00, v01);
                if (r0r + 8 < M)
                    *(__half2*)(Ch + cbase + (size_t)(r0r+8)*HD + cc) =
                        __floats2half2_rn(v10, v11);
            } else {
                float* Cf = (float*)Cv;
                if (r0r < M)
                    *(float2*)(Cf + cbase + (size_t)r0r*HD + cc) = make_float2(v00, v01);
                if (r0r + 8 < M)
                    *(float2*)(Cf + cbase + (size_t)(r0r+8)*HD + cc) = make_float2(v10, v11);
            }
        }
    }
}

// ---------------- edge aggregation: one warp per (node, relation) ----------------
__global__ void k_edge() {
    int r = blockIdx.y;
    int warp = threadIdx.x >> 5, lane = threadIdx.x & 31;
    int n = blockIdx.x*8 + warp;
    int idx = r*NN + n;
    float acc[8];
    #pragma unroll
    for (int k = 0; k < 8; k++) acc[k] = 0.f;

    int deg = g_counts[idx];
    if (deg > 0) {
        int base = g_rowptr[idx];

        // pass 1: denominators = sum |ew| per head (lane-strided, coalesced)
        float d0 = 0.f, d1 = 0.f, d2 = 0.f, d3 = 0.f;
        for (int j = lane; j < deg; j += 32) {
            float4 e = g_ew[base + j];
            d0 += fabsf(e.x); d1 += fabsf(e.y); d2 += fabsf(e.z); d3 += fabsf(e.w);
        }
        #pragma unroll
        for (int o = 16; o; o >>= 1) {
            d0 += __shfl_xor_sync(0xffffffffu, d0, o);
            d1 += __shfl_xor_sync(0xffffffffu, d1, o);
            d2 += __shfl_xor_sync(0xffffffffu, d2, o);
            d3 += __shfl_xor_sync(0xffffffffu, d3, o);
        }
        int hl = lane >> 3;
        float invh = 1.f / ((hl == 0) ? d0 : (hl == 1) ? d1 : (hl == 2) ? d2 : d3);

        const __half* hwr = g_hw16 + (size_t)r*NN*HD;
        const int*   sl = g_srclist + base;
        const float4* ew = g_ew + base;
        int co = lane*8;

        auto pick = [&](float4 e) -> float {
            return (hl == 0) ? e.x : (hl == 1) ? e.y : (hl == 2) ? e.z : e.w;
        };
        auto accum = [&](uint4 v, float wh) {
            float2 x0 = __half22float2(*(__half2*)&v.x);
            float2 x1 = __half22float2(*(__half2*)&v.y);
            float2 x2 = __half22float2(*(__half2*)&v.z);
            float2 x3 = __half22float2(*(__half2*)&v.w);
            acc[0] += wh*x0.x; acc[1] += wh*x0.y; acc[2] += wh*x1.x; acc[3] += wh*x1.y;
            acc[4] += wh*x2.x; acc[5] += wh*x2.y; acc[6] += wh*x3.x; acc[7] += wh*x3.y;
        };

        int j = 0;
        for (; j + 4 <= deg; j += 4) {
            int s0 = sl[j], s1 = sl[j+1], s2 = sl[j+2], s3 = sl[j+3];
            float4 e0 = ew[j], e1 = ew[j+1], e2 = ew[j+2], e3 = ew[j+3];
            uint4 v0 = *(const uint4*)(hwr + (size_t)s0*HD + co);
            uint4 v1 = *(const uint4*)(hwr + (size_t)s1*HD + co);
            uint4 v2 = *(const uint4*)(hwr + (size_t)s2*HD + co);
            uint4 v3 = *(const uint4*)(hwr + (size_t)s3*HD + co);
            accum(v0, pick(e0)*invh);
            accum(v1, pick(e1)*invh);
            accum(v2, pick(e2)*invh);
            accum(v3, pick(e3)*invh);
        }
        for (; j < deg; j++) {
            int s0 = sl[j];
            float4 e0 = ew[j];
            uint4 v0 = *(const uint4*)(hwr + (size_t)s0*HD + co);
            accum(v0, pick(e0)*invh);
        }
    }
    // write fp16 (feeds GEMM2 A operand)
    __half hi[8];
    #pragma unroll
    for (int k = 0; k < 8; k++) hi[k] = __float2half_rn(acc[k]);
    size_t ofs = (size_t)n*(RRD*HD) + r*HD + lane*8;
    *(uint4*)(g_a2hi + ofs) = *(uint4*)hi;
}

// ---------------- launch ----------------
extern "C" void kernel_launch(void* const* d_in, const int* in_sizes, int n_in,
                              void* d_out, int out_size) {
    const float* h    = (const float*)d_in[0];
    const float* dW   = (const float*)d_in[1];
    const float* db   = (const float*)d_in[2];
    const float* fW   = (const float*)d_in[3];
    const float* fb   = (const float*)d_in[4];
    const float* wW   = (const float*)d_in[5];
    const float* wb   = (const float*)d_in[6];
    const float* aW   = (const float*)d_in[7];
    const float* ab   = (const float*)d_in[8];
    const float* linW = (const float*)d_in[9];
    const float* linb = (const float*)d_in[10];
    const int*   src  = (const int*)d_in[11];
    const int*   dst  = (const int*)d_in[12];

    __half *hw16, *hhi, *a2hi, *w1h, *w2h;
    cudaGetSymbolAddress((void**)&hw16, g_hw16);
    cudaGetSymbolAddress((void**)&hhi,  g_hhi);
    cudaGetSymbolAddress((void**)&a2hi, g_a2hi);
    cudaGetSymbolAddress((void**)&w1h,  g_w1h);
    cudaGetSymbolAddress((void**)&w2h,  g_w2h);

    const int smem_bytes = 3*STAGEE*sizeof(__half);   // 61440
    cudaFuncSetAttribute(k_gemm_mma, cudaFuncAttributeMaxDynamicSharedMemorySize, smem_bytes);

    // GEMM1 kept at launch index 3 (the slot ncu captures).
    k_vecs<<<1, 128>>>(dW, db, fW, fb, wW, wb, aW, ab);
    k_node<<<NN/8, 256>>>(h);          // also emits g_hhi (fused split_h)
    k_transB<<<(RRD*HD*IND + HD*RRD*HD + 255)/256, 256>>>(wW, linW);

    // GEMM1: hw[r] = h @ wW[r] + wb[r]  -> fp16 (M=50000, K=128, N=256, z=R)
    dim3 g1((NN + 127)/128, 2, RRD);
    k_gemm_mma<<<g1, 256, smem_bytes>>>(hhi, w1h, wb, hw16,
                                        NN, IND, 1,
                                        (long long)HD*IND, (long long)HD,
                                        (long long)NN*HD);

    k_zero<<<(RN + 255)/256, 256>>>();
    k_hist<<<(RE + 255)/256, 256>>>(dst);
    k_scan1<<<NB, 1024>>>();
    k_scan2<<<1, 256>>>();
    k_scan3<<<NB, 1024>>>();
    k_scatter<<<(RE + 255)/256, 256>>>(src, dst);

    dim3 g2(NN/8, RRD);
    k_edge<<<g2, 256>>>();

    // GEMM2: out = a2 @ linW + linb -> fp32 (M=50000, K=768, N=256)
    dim3 g3((NN + 127)/128, 2, 1);
    k_gemm_mma<<<g3, 256, smem_bytes>>>(a2hi, w2h, linb, d_out,
                                        NN, RRD*HD, 0, 0, 0, 0);
}